// round 1
// baseline (speedup 1.0000x reference)
#include <cuda_runtime.h>
#include <cuda_bf16.h>
#include <math.h>

// ---------------- problem constants ----------------
#define BB      2
#define CC      1024
#define TT      1024
#define TOKS    (BB * TT)          // 2048
#define DIN     2048
#define DSTATE  16
#define DTRANK  64
#define XDBL    96                 // DT_RANK + 2*D_STATE
#define DCONV   4

// ---------------- scratch (allocation-free) ----------------
__device__ float g_xn  [TOKS * CC];        // normalized input        8.4 MB
__device__ float g_xz  [TOKS * 2 * DIN];   // in_proj out (x_in|z)   33.6 MB
__device__ float g_xc  [TOKS * DIN];       // conv+silu out          16.8 MB
__device__ float g_xdbl[TOKS * XDBL];      // x_proj out              0.8 MB
__device__ float g_dt  [TOKS * DIN];       // softplus(dt)           16.8 MB
__device__ float g_y   [TOKS * DIN];       // gated ssm out          16.8 MB

// ---------------- LayerNorm over C, reading x (B,C,T) ----------------
__global__ __launch_bounds__(256) void ln_kernel(const float* __restrict__ x,
                                                 const float* __restrict__ w,
                                                 const float* __restrict__ bvec) {
    int tok = blockIdx.x;
    int b = tok >> 10, t = tok & 1023;
    const float* xp = x + (size_t)b * CC * TT + t;   // element c at xp[c*TT]

    float vals[4];
    float s = 0.f, s2 = 0.f;
#pragma unroll
    for (int i = 0; i < 4; i++) {
        int c = threadIdx.x + i * 256;
        float v = __ldg(xp + (size_t)c * TT);
        vals[i] = v;
        s += v;
        s2 = fmaf(v, v, s2);
    }
#pragma unroll
    for (int o = 16; o; o >>= 1) {
        s  += __shfl_xor_sync(0xffffffffu, s,  o);
        s2 += __shfl_xor_sync(0xffffffffu, s2, o);
    }
    __shared__ float sh[16];
    int wp = threadIdx.x >> 5, ln = threadIdx.x & 31;
    if (ln == 0) { sh[wp] = s; sh[8 + wp] = s2; }
    __syncthreads();
    float S = 0.f, S2 = 0.f;
#pragma unroll
    for (int i = 0; i < 8; i++) { S += sh[i]; S2 += sh[8 + i]; }
    float mu  = S * (1.f / 1024.f);
    float var = S2 * (1.f / 1024.f) - mu * mu;
    float rs  = rsqrtf(var + 1e-5f);

    float* op = g_xn + (size_t)tok * CC;
#pragma unroll
    for (int i = 0; i < 4; i++) {
        int c = threadIdx.x + i * 256;
        op[c] = (vals[i] - mu) * rs * w[c] + bvec[c];
    }
}

// ---------------- generic fp32 GEMM: C[M,N] = A[M,K] @ W[N,K]^T ----------------
// OP 0: plain store to Cout[m*ldc+n]
// OP 1: softplus(v + bias[n]) -> Cout
// OP 2: out[b, n, t] = v + resid[b, n, t]   (transposed store with residual)
#define GBM 128
#define GBN 64
#define GBK 16

template <int OP>
__global__ __launch_bounds__(256) void gemm_kernel(const float* __restrict__ A, int lda,
                                                   const float* __restrict__ W, int ldw,
                                                   float* __restrict__ Cout, int ldc,
                                                   int M, int N, int K,
                                                   const float* __restrict__ bias,
                                                   const float* __restrict__ resid) {
    __shared__ float As[GBK][GBM];
    __shared__ float Bs[GBK][GBN];

    int tid = threadIdx.x;
    int tx = tid & 15;        // N dir, 4 cols each
    int ty = tid >> 4;        // M dir, 8 rows each
    int rowBase = blockIdx.y * GBM;
    int colBase = blockIdx.x * GBN;

    float acc[8][4];
#pragma unroll
    for (int i = 0; i < 8; i++)
#pragma unroll
        for (int j = 0; j < 4; j++) acc[i][j] = 0.f;

    for (int k0 = 0; k0 < K; k0 += GBK) {
        // A tile: 128x16 = 512 float4, 2 per thread
#pragma unroll
        for (int i = 0; i < 2; i++) {
            int v = tid + i * 256;
            int r = v >> 2;
            int kc = (v & 3) << 2;
            float4 av = *(const float4*)(A + (size_t)(rowBase + r) * lda + k0 + kc);
            As[kc + 0][r] = av.x; As[kc + 1][r] = av.y;
            As[kc + 2][r] = av.z; As[kc + 3][r] = av.w;
        }
        // W tile: 64x16 = 256 float4, 1 per thread
        {
            int r = tid >> 2;
            int kc = (tid & 3) << 2;
            int n = colBase + r;
            float4 bv = make_float4(0.f, 0.f, 0.f, 0.f);
            if (n < N) bv = *(const float4*)(W + (size_t)n * ldw + k0 + kc);
            Bs[kc + 0][r] = bv.x; Bs[kc + 1][r] = bv.y;
            Bs[kc + 2][r] = bv.z; Bs[kc + 3][r] = bv.w;
        }
        __syncthreads();

#pragma unroll
        for (int kk = 0; kk < GBK; kk++) {
            float a[8], bcol[4];
#pragma unroll
            for (int i = 0; i < 8; i++) a[i] = As[kk][ty * 8 + i];
#pragma unroll
            for (int j = 0; j < 4; j++) bcol[j] = Bs[kk][tx * 4 + j];
#pragma unroll
            for (int i = 0; i < 8; i++)
#pragma unroll
                for (int j = 0; j < 4; j++) acc[i][j] = fmaf(a[i], bcol[j], acc[i][j]);
        }
        __syncthreads();
    }

#pragma unroll
    for (int i = 0; i < 8; i++) {
        int m = rowBase + ty * 8 + i;
#pragma unroll
        for (int j = 0; j < 4; j++) {
            int n = colBase + tx * 4 + j;
            if (n >= N) continue;
            float v = acc[i][j];
            if (OP == 0) {
                Cout[(size_t)m * ldc + n] = v;
            } else if (OP == 1) {
                v += bias[n];
                float sp = (v > 20.f) ? v : log1pf(__expf(v));
                Cout[(size_t)m * ldc + n] = sp;
            } else {  // OP == 2: transposed store + residual
                int b = m >> 10, t = m & 1023;
                size_t oi = (size_t)b * CC * TT + (size_t)n * TT + t;
                Cout[oi] = v + resid[oi];
            }
        }
    }
}

// ---------------- depthwise causal conv (k=4) + SiLU ----------------
__global__ __launch_bounds__(256) void conv_silu_kernel(const float* __restrict__ conv_w,
                                                        const float* __restrict__ conv_b) {
    int idx = blockIdx.x * 256 + threadIdx.x;     // tok*DIN + d
    int d = idx & (DIN - 1);
    int tok = idx >> 11;
    int b = tok >> 10, t = tok & 1023;

    float w0 = conv_w[d * DCONV + 0];
    float w1 = conv_w[d * DCONV + 1];
    float w2 = conv_w[d * DCONV + 2];
    float w3 = conv_w[d * DCONV + 3];

    const float* xin = g_xz + (size_t)(b * TT) * (2 * DIN) + d;  // x_in part, stride 4096 per t
    float v = conv_b[d];
    if (t >= 3) v = fmaf(w0, xin[(size_t)(t - 3) * (2 * DIN)], v);
    if (t >= 2) v = fmaf(w1, xin[(size_t)(t - 2) * (2 * DIN)], v);
    if (t >= 1) v = fmaf(w2, xin[(size_t)(t - 1) * (2 * DIN)], v);
    v = fmaf(w3, xin[(size_t)t * (2 * DIN)], v);

    float sig = 1.f / (1.f + __expf(-v));
    g_xc[idx] = v * sig;
}

// ---------------- selective scan: lane-per-state, 2 channels per warp ----------------
__global__ __launch_bounds__(256) void scan_kernel(const float* __restrict__ A_log,
                                                   const float* __restrict__ Dvec) {
    int tid = threadIdx.x;
    int lane = tid & 31;
    int warp = tid >> 5;                 // 8 warps/block
    int s = lane & 15;                   // state index
    int chInWarp = lane >> 4;            // 0/1
    int g = blockIdx.x * 16 + warp * 2 + chInWarp;   // global channel 0..4095
    int b = g >> 11;
    int d = g & (DIN - 1);

    float A_s = -__expf(A_log[d * DSTATE + s]);
    float Dd  = Dvec[d];

    const float* dtp = g_dt   + (size_t)(b * TT) * DIN + d;
    const float* xcp = g_xc   + (size_t)(b * TT) * DIN + d;
    const float* dbp = g_xdbl + (size_t)(b * TT) * XDBL;
    const float* zp  = g_xz   + (size_t)(b * TT) * (2 * DIN) + DIN + d;
    float*       yp  = g_y    + (size_t)(b * TT) * DIN + d;

    float h = 0.f;
    for (int t = 0; t < TT; t++) {
        float dtv = __ldg(dtp + (size_t)t * DIN);
        float xv  = __ldg(xcp + (size_t)t * DIN);
        float Bv  = __ldg(dbp + (size_t)t * XDBL + DTRANK + s);
        float Cv  = __ldg(dbp + (size_t)t * XDBL + DTRANK + DSTATE + s);

        float dA = __expf(dtv * A_s);
        h = fmaf(dA, h, dtv * Bv * xv);
        float p = h * Cv;
        p += __shfl_xor_sync(0xffffffffu, p, 8);
        p += __shfl_xor_sync(0xffffffffu, p, 4);
        p += __shfl_xor_sync(0xffffffffu, p, 2);
        p += __shfl_xor_sync(0xffffffffu, p, 1);
        if (s == 0) {
            float zv  = __ldg(zp + (size_t)t * (2 * DIN));
            float sig = 1.f / (1.f + __expf(-zv));
            yp[(size_t)t * DIN] = (p + Dd * xv) * (zv * sig);
        }
    }
}

// ---------------- launch ----------------
extern "C" void kernel_launch(void* const* d_in, const int* in_sizes, int n_in,
                              void* d_out, int out_size) {
    const float* x          = (const float*)d_in[0];
    const float* norm_w     = (const float*)d_in[1];
    const float* norm_b     = (const float*)d_in[2];
    const float* in_proj_w  = (const float*)d_in[3];   // (4096, 1024)
    const float* conv_w     = (const float*)d_in[4];   // (2048, 1, 4)
    const float* conv_b     = (const float*)d_in[5];
    const float* x_proj_w   = (const float*)d_in[6];   // (96, 2048)
    const float* dt_proj_w  = (const float*)d_in[7];   // (2048, 64)
    const float* dt_proj_b  = (const float*)d_in[8];
    const float* A_log      = (const float*)d_in[9];   // (2048, 16)
    const float* Dvec       = (const float*)d_in[10];  // (2048,)
    const float* out_proj_w = (const float*)d_in[11];  // (1024, 2048)
    float* out = (float*)d_out;

    float *xn, *xz, *xc, *xdbl, *dt, *y;
    cudaGetSymbolAddress((void**)&xn,   g_xn);
    cudaGetSymbolAddress((void**)&xz,   g_xz);
    cudaGetSymbolAddress((void**)&xc,   g_xc);
    cudaGetSymbolAddress((void**)&xdbl, g_xdbl);
    cudaGetSymbolAddress((void**)&dt,   g_dt);
    cudaGetSymbolAddress((void**)&y,    g_y);

    // 1. LayerNorm
    ln_kernel<<<TOKS, 256>>>(x, norm_w, norm_b);

    // 2. in_proj: xz[2048, 4096] = xn[2048,1024] @ in_proj_w^T
    gemm_kernel<0><<<dim3((2 * DIN) / GBN, TOKS / GBM), 256>>>(
        xn, CC, in_proj_w, CC, xz, 2 * DIN, TOKS, 2 * DIN, CC, nullptr, nullptr);

    // 3. depthwise conv + SiLU
    conv_silu_kernel<<<(TOKS * DIN) / 256, 256>>>(conv_w, conv_b);

    // 4. x_proj: xdbl[2048, 96] = xc[2048,2048] @ x_proj_w^T
    gemm_kernel<0><<<dim3((XDBL + GBN - 1) / GBN, TOKS / GBM), 256>>>(
        xc, DIN, x_proj_w, DIN, xdbl, XDBL, TOKS, XDBL, DIN, nullptr, nullptr);

    // 5. dt_proj + softplus: dt[2048, 2048] = softplus(xdbl[:, :64] @ dt_proj_w^T + b)
    gemm_kernel<1><<<dim3(DIN / GBN, TOKS / GBM), 256>>>(
        xdbl, XDBL, dt_proj_w, DTRANK, dt, DIN, TOKS, DIN, DTRANK, dt_proj_b, nullptr);

    // 6. selective scan + D*x_c + silu(z) gate
    scan_kernel<<<(BB * DIN) / 16, 256>>>(A_log, Dvec);

    // 7. out_proj + residual, transposed store into (B, C, T)
    gemm_kernel<2><<<dim3(CC / GBN, TOKS / GBM), 256>>>(
        y, DIN, out_proj_w, DIN, out, 0, TOKS, CC, DIN, nullptr, x);
}

// round 2
// speedup vs baseline: 1.2576x; 1.2576x over previous
#include <cuda_runtime.h>
#include <cuda_bf16.h>
#include <math.h>
#include <stdint.h>

// ---------------- problem constants ----------------
#define BB      2
#define CC      1024
#define TT      1024
#define TOKS    (BB * TT)          // 2048
#define DIN     2048
#define DSTATE  16
#define DTRANK  64
#define XDBL    96                 // DT_RANK + 2*D_STATE
#define DCONV   4
#define SPLITK  8

// ---------------- fp32 scratch ----------------
__device__ float g_xz  [TOKS * 2 * DIN];
__device__ float g_xc  [TOKS * DIN];
__device__ float g_xdbl[TOKS * XDBL];
__device__ float g_dt  [TOKS * DIN];
__device__ float g_part[SPLITK * TOKS * XDBL];

// ---------------- bf16 split-precision scratch ----------------
__device__ __nv_bfloat16 e_xn [TOKS * 3 * CC];
__device__ __nv_bfloat16 e_w1 [2 * DIN * 3 * CC];
__device__ __nv_bfloat16 e_xc [TOKS * 3 * DIN];
__device__ __nv_bfloat16 e_w2 [XDBL * 3 * DIN];
__device__ __nv_bfloat16 e_dtr[TOKS * 3 * DTRANK];
__device__ __nv_bfloat16 e_w3 [DIN * 3 * DTRANK];
__device__ __nv_bfloat16 e_y  [TOKS * 3 * DIN];
__device__ __nv_bfloat16 e_w4 [CC * 3 * DIN];

__device__ __forceinline__ void split2(float v, __nv_bfloat16& hi, __nv_bfloat16& lo) {
    hi = __float2bfloat16(v);
    lo = __float2bfloat16(v - __bfloat162float(hi));
}

// ---------------- LayerNorm -> e_xn ext (hi,hi,lo) ----------------
__global__ __launch_bounds__(256) void ln_kernel(const float* __restrict__ x,
                                                 const float* __restrict__ w,
                                                 const float* __restrict__ bvec) {
    int tok = blockIdx.x;
    int b = tok >> 10, t = tok & 1023;
    const float* xp = x + (size_t)b * CC * TT + t;

    float vals[4];
    float s = 0.f, s2 = 0.f;
#pragma unroll
    for (int i = 0; i < 4; i++) {
        int c = threadIdx.x + i * 256;
        float v = __ldg(xp + (size_t)c * TT);
        vals[i] = v;
        s += v;
        s2 = fmaf(v, v, s2);
    }
#pragma unroll
    for (int o = 16; o; o >>= 1) {
        s  += __shfl_xor_sync(0xffffffffu, s,  o);
        s2 += __shfl_xor_sync(0xffffffffu, s2, o);
    }
    __shared__ float sh[16];
    int wp = threadIdx.x >> 5, ln = threadIdx.x & 31;
    if (ln == 0) { sh[wp] = s; sh[8 + wp] = s2; }
    __syncthreads();
    float S = 0.f, S2 = 0.f;
#pragma unroll
    for (int i = 0; i < 8; i++) { S += sh[i]; S2 += sh[8 + i]; }
    float mu  = S * (1.f / 1024.f);
    float var = S2 * (1.f / 1024.f) - mu * mu;
    float rs  = rsqrtf(var + 1e-5f);

    __nv_bfloat16* op = e_xn + (size_t)tok * 3 * CC;
#pragma unroll
    for (int i = 0; i < 4; i++) {
        int c = threadIdx.x + i * 256;
        float v = (vals[i] - mu) * rs * w[c] + bvec[c];
        __nv_bfloat16 hi, lo; split2(v, hi, lo);
        op[c] = hi; op[CC + c] = hi; op[2 * CC + c] = lo;
    }
}

// ---------------- conversions: MODE 0 weights [hi,lo,hi], MODE 1 acts [hi,hi,lo] ----------------
template <int MODE>
__global__ __launch_bounds__(256) void convert_kernel(const float* __restrict__ in,
                                                      __nv_bfloat16* __restrict__ out,
                                                      int K, int total) {
    int i = blockIdx.x * 256 + threadIdx.x;
    if (i >= total) return;
    int r = i / K, k = i - r * K;
    float v = in[i];
    __nv_bfloat16 hi, lo; split2(v, hi, lo);
    __nv_bfloat16* o = out + (size_t)r * 3 * K;
    if (MODE == 0) { o[k] = hi; o[K + k] = lo; o[2 * K + k] = hi; }
    else           { o[k] = hi; o[K + k] = hi; o[2 * K + k] = lo; }
}

__global__ __launch_bounds__(256) void convert_dtr_kernel() {
    int i = blockIdx.x * 256 + threadIdx.x;
    int tok = i >> 6, k = i & 63;
    float v = g_xdbl[tok * XDBL + k];
    __nv_bfloat16 hi, lo; split2(v, hi, lo);
    __nv_bfloat16* o = e_dtr + (size_t)tok * 3 * DTRANK;
    o[k] = hi; o[DTRANK + k] = hi; o[2 * DTRANK + k] = lo;
}

// ---------------- tensor-core bf16 GEMM ----------------
#define GBM 128
#define GBN 128
#define GBK 32
#define SKP 40      // padded smem row stride in bf16 (80 B) — ldmatrix conflict-free

__device__ __forceinline__ uint32_t smem_u32(const void* p) {
    uint32_t a;
    asm("{ .reg .u64 t; cvta.to.shared.u64 t, %1; cvt.u32.u64 %0, t; }" : "=r"(a) : "l"(p));
    return a;
}
__device__ __forceinline__ void cp16(uint32_t dst, const void* src, bool pred) {
    int sz = pred ? 16 : 0;
    asm volatile("cp.async.cg.shared.global [%0], [%1], 16, %2;\n" :: "r"(dst), "l"(src), "r"(sz));
}
__device__ __forceinline__ void ldsm4(uint32_t& r0, uint32_t& r1, uint32_t& r2, uint32_t& r3,
                                      uint32_t addr) {
    asm volatile("ldmatrix.sync.aligned.m8n8.x4.shared.b16 {%0,%1,%2,%3}, [%4];"
                 : "=r"(r0), "=r"(r1), "=r"(r2), "=r"(r3) : "r"(addr));
}
__device__ __forceinline__ void mma16816(float* c, const uint32_t* a, const uint32_t* b) {
    asm volatile("mma.sync.aligned.m16n8k16.row.col.f32.bf16.bf16.f32 "
                 "{%0,%1,%2,%3}, {%4,%5,%6,%7}, {%8,%9}, {%0,%1,%2,%3};"
                 : "+f"(c[0]), "+f"(c[1]), "+f"(c[2]), "+f"(c[3])
                 : "r"(a[0]), "r"(a[1]), "r"(a[2]), "r"(a[3]), "r"(b[0]), "r"(b[1]));
}

// OP 0 plain | OP 1 softplus+bias | OP 2 transpose+residual | OP 3 split-K partials
template <int OP>
__global__ __launch_bounds__(256) void gemm_bf16(const __nv_bfloat16* __restrict__ A, int lda,
                                                 const __nv_bfloat16* __restrict__ W, int ldw,
                                                 float* __restrict__ C, int ldc,
                                                 int M, int N, int Kext,
                                                 const float* __restrict__ bias,
                                                 const float* __restrict__ resid) {
    __shared__ __nv_bfloat16 sA[2][GBM * SKP];
    __shared__ __nv_bfloat16 sB[2][GBN * SKP];

    int tid = threadIdx.x;
    int lane = tid & 31, warp = tid >> 5;
    int wm = warp & 3;
    int wn = warp >> 2;
    int rowBase = blockIdx.y * GBM;
    int colBase = blockIdx.x * GBN;

    int kStart = 0, kEnd = Kext;
    if (OP == 3) {
        int chunk = Kext / SPLITK;
        kStart = blockIdx.z * chunk;
        kEnd   = kStart + chunk;
        C += (size_t)blockIdx.z * M * ldc;
    }

    uint32_t sAb = smem_u32(sA);
    uint32_t sBb = smem_u32(sB);
    const uint32_t stA = GBM * SKP * 2;
    const uint32_t stB = GBN * SKP * 2;

    float acc[2][8][4];
#pragma unroll
    for (int i = 0; i < 2; i++)
#pragma unroll
        for (int j = 0; j < 8; j++)
#pragma unroll
            for (int k = 0; k < 4; k++) acc[i][j][k] = 0.f;

    auto load_tiles = [&](int stage, int k0) {
#pragma unroll
        for (int i = 0; i < 2; i++) {
            int c = tid + i * 256;
            int row = c >> 2, cc = c & 3;
            const __nv_bfloat16* src = A + (size_t)(rowBase + row) * lda + k0 + cc * 8;
            cp16(sAb + stage * stA + row * (SKP * 2) + cc * 16, src, true);
        }
#pragma unroll
        for (int i = 0; i < 2; i++) {
            int c = tid + i * 256;
            int row = c >> 2, cc = c & 3;
            bool ok = (colBase + row) < N;
            const __nv_bfloat16* src = W + (ok ? (size_t)(colBase + row) * ldw : 0) + k0 + cc * 8;
            cp16(sBb + stage * stB + row * (SKP * 2) + cc * 16, src, ok);
        }
        asm volatile("cp.async.commit_group;\n");
    };

    int nTiles = (kEnd - kStart) / GBK;
    load_tiles(0, kStart);
    int stage = 0;

    for (int t = 0; t < nTiles; t++) {
        asm volatile("cp.async.wait_group 0;\n");
        __syncthreads();
        if (t + 1 < nTiles) load_tiles(stage ^ 1, kStart + (t + 1) * GBK);

        uint32_t aBase = sAb + stage * stA;
        uint32_t bBase = sBb + stage * stB;
#pragma unroll
        for (int kk = 0; kk < 2; kk++) {
            uint32_t afr[2][4];
#pragma unroll
            for (int mt = 0; mt < 2; mt++) {
                int row = wm * 32 + mt * 16 + (lane & 15);
                uint32_t ad = aBase + row * (SKP * 2) + kk * 32 + (lane >> 4) * 16;
                ldsm4(afr[mt][0], afr[mt][1], afr[mt][2], afr[mt][3], ad);
            }
            uint32_t bfr[8][2];
#pragma unroll
            for (int p = 0; p < 4; p++) {
                int row = wn * 64 + p * 16 + (lane & 15);
                uint32_t bd = bBase + row * (SKP * 2) + kk * 32 + (lane >> 4) * 16;
                uint32_t r0, r1, r2, r3;
                ldsm4(r0, r1, r2, r3, bd);
                bfr[2 * p][0] = r0; bfr[2 * p + 1][0] = r1;
                bfr[2 * p][1] = r2; bfr[2 * p + 1][1] = r3;
            }
#pragma unroll
            for (int mt = 0; mt < 2; mt++)
#pragma unroll
                for (int nt = 0; nt < 8; nt++)
                    mma16816(acc[mt][nt], afr[mt], bfr[nt]);
        }
        stage ^= 1;
    }

#pragma unroll
    for (int mt = 0; mt < 2; mt++) {
        int r0 = rowBase + wm * 32 + mt * 16 + (lane >> 2);
#pragma unroll
        for (int nt = 0; nt < 8; nt++) {
            int c0 = colBase + wn * 64 + nt * 8 + (lane & 3) * 2;
            float* a4 = acc[mt][nt];
#pragma unroll
            for (int e = 0; e < 4; e++) {
                int m = r0 + ((e >= 2) ? 8 : 0);
                int n = c0 + (e & 1);
                if (n >= N) continue;
                float v = a4[e];
                if (OP == 0 || OP == 3) {
                    C[(size_t)m * ldc + n] = v;
                } else if (OP == 1) {
                    v += bias[n];
                    float sp = (v > 20.f) ? v : log1pf(__expf(v));
                    C[(size_t)m * ldc + n] = sp;
                } else {
                    int b = m >> 10, tt = m & 1023;
                    size_t oi = (size_t)b * CC * TT + (size_t)n * TT + tt;
                    C[oi] = v + resid[oi];
                }
            }
        }
    }
}

__global__ __launch_bounds__(256) void reduce_part_kernel() {
    int i = blockIdx.x * 256 + threadIdx.x;
    if (i >= TOKS * XDBL) return;
    float s = 0.f;
#pragma unroll
    for (int z = 0; z < SPLITK; z++) s += g_part[(size_t)z * TOKS * XDBL + i];
    g_xdbl[i] = s;
}

// ---------------- conv + SiLU ----------------
__global__ __launch_bounds__(256) void conv_silu_kernel(const float* __restrict__ conv_w,
                                                        const float* __restrict__ conv_b) {
    int idx = blockIdx.x * 256 + threadIdx.x;
    int d = idx & (DIN - 1);
    int tok = idx >> 11;
    int b = tok >> 10, t = tok & 1023;

    float w0 = conv_w[d * DCONV + 0];
    float w1 = conv_w[d * DCONV + 1];
    float w2 = conv_w[d * DCONV + 2];
    float w3 = conv_w[d * DCONV + 3];

    const float* xin = g_xz + (size_t)(b * TT) * (2 * DIN) + d;
    float v = conv_b[d];
    if (t >= 3) v = fmaf(w0, xin[(size_t)(t - 3) * (2 * DIN)], v);
    if (t >= 2) v = fmaf(w1, xin[(size_t)(t - 2) * (2 * DIN)], v);
    if (t >= 1) v = fmaf(w2, xin[(size_t)(t - 1) * (2 * DIN)], v);
    v = fmaf(w3, xin[(size_t)t * (2 * DIN)], v);

    float sig = 1.f / (1.f + __expf(-v));
    float o = v * sig;
    g_xc[idx] = o;
    __nv_bfloat16 hi, lo; split2(o, hi, lo);
    __nv_bfloat16* op = e_xc + (size_t)tok * 3 * DIN + d;
    op[0] = hi; op[DIN] = hi; op[2 * DIN] = lo;
}

// ---------------- selective scan ----------------
__global__ __launch_bounds__(256) void scan_kernel(const float* __restrict__ A_log,
                                                   const float* __restrict__ Dvec) {
    int tid = threadIdx.x;
    int lane = tid & 31;
    int warp = tid >> 5;
    int s = lane & 15;
    int chInWarp = lane >> 4;
    int g = blockIdx.x * 16 + warp * 2 + chInWarp;
    int b = g >> 11;
    int d = g & (DIN - 1);

    float A_s = -__expf(A_log[d * DSTATE + s]);
    float Dd  = Dvec[d];

    const float* dtp = g_dt   + (size_t)(b * TT) * DIN + d;
    const float* xcp = g_xc   + (size_t)(b * TT) * DIN + d;
    const float* dbp = g_xdbl + (size_t)(b * TT) * XDBL;
    const float* zp  = g_xz   + (size_t)(b * TT) * (2 * DIN) + DIN + d;
    __nv_bfloat16* yp = e_y   + (size_t)(b * TT) * 3 * DIN + d;

    float h = 0.f;
    for (int t = 0; t < TT; t++) {
        float dtv = __ldg(dtp + (size_t)t * DIN);
        float xv  = __ldg(xcp + (size_t)t * DIN);
        float Bv  = __ldg(dbp + (size_t)t * XDBL + DTRANK + s);
        float Cv  = __ldg(dbp + (size_t)t * XDBL + DTRANK + DSTATE + s);

        float dA = __expf(dtv * A_s);
        h = fmaf(dA, h, dtv * Bv * xv);
        float p = h * Cv;
        p += __shfl_xor_sync(0xffffffffu, p, 8);
        p += __shfl_xor_sync(0xffffffffu, p, 4);
        p += __shfl_xor_sync(0xffffffffu, p, 2);
        p += __shfl_xor_sync(0xffffffffu, p, 1);
        if (s == 0) {
            float zv  = __ldg(zp + (size_t)t * (2 * DIN));
            float sig = 1.f / (1.f + __expf(-zv));
            float yv  = (p + Dd * xv) * (zv * sig);
            __nv_bfloat16 hi, lo; split2(yv, hi, lo);
            __nv_bfloat16* o = yp + (size_t)t * 3 * DIN;
            o[0] = hi; o[DIN] = hi; o[2 * DIN] = lo;
        }
    }
}

// ---------------- launch ----------------
extern "C" void kernel_launch(void* const* d_in, const int* in_sizes, int n_in,
                              void* d_out, int out_size) {
    const float* x          = (const float*)d_in[0];
    const float* norm_w     = (const float*)d_in[1];
    const float* norm_b     = (const float*)d_in[2];
    const float* in_proj_w  = (const float*)d_in[3];
    const float* conv_w     = (const float*)d_in[4];
    const float* conv_b     = (const float*)d_in[5];
    const float* x_proj_w   = (const float*)d_in[6];
    const float* dt_proj_w  = (const float*)d_in[7];
    const float* dt_proj_b  = (const float*)d_in[8];
    const float* A_log      = (const float*)d_in[9];
    const float* Dvec       = (const float*)d_in[10];
    const float* out_proj_w = (const float*)d_in[11];
    float* out = (float*)d_out;

    float *xz, *xdbl, *dt, *part;
    __nv_bfloat16 *exn, *ew1, *exc, *ew2, *edtr, *ew3, *ey, *ew4;
    cudaGetSymbolAddress((void**)&xz,   g_xz);
    cudaGetSymbolAddress((void**)&xdbl, g_xdbl);
    cudaGetSymbolAddress((void**)&dt,   g_dt);
    cudaGetSymbolAddress((void**)&part, g_part);
    cudaGetSymbolAddress((void**)&exn,  e_xn);
    cudaGetSymbolAddress((void**)&ew1,  e_w1);
    cudaGetSymbolAddress((void**)&exc,  e_xc);
    cudaGetSymbolAddress((void**)&ew2,  e_w2);
    cudaGetSymbolAddress((void**)&edtr, e_dtr);
    cudaGetSymbolAddress((void**)&ew3,  e_w3);
    cudaGetSymbolAddress((void**)&ey,   e_y);
    cudaGetSymbolAddress((void**)&ew4,  e_w4);

    convert_kernel<0><<<(2 * DIN * CC + 255) / 256, 256>>>(in_proj_w,  ew1, CC,     2 * DIN * CC);
    convert_kernel<0><<<(XDBL * DIN + 255) / 256, 256>>>(x_proj_w,    ew2, DIN,    XDBL * DIN);
    convert_kernel<0><<<(DIN * DTRANK + 255) / 256, 256>>>(dt_proj_w, ew3, DTRANK, DIN * DTRANK);
    convert_kernel<0><<<(CC * DIN + 255) / 256, 256>>>(out_proj_w,    ew4, DIN,    CC * DIN);

    ln_kernel<<<TOKS, 256>>>(x, norm_w, norm_b);

    gemm_bf16<0><<<dim3((2 * DIN) / GBN, TOKS / GBM), 256>>>(
        exn, 3 * CC, ew1, 3 * CC, xz, 2 * DIN, TOKS, 2 * DIN, 3 * CC, nullptr, nullptr);

    conv_silu_kernel<<<(TOKS * DIN) / 256, 256>>>(conv_w, conv_b);

    gemm_bf16<3><<<dim3(1, TOKS / GBM, SPLITK), 256>>>(
        exc, 3 * DIN, ew2, 3 * DIN, part, XDBL, TOKS, XDBL, 3 * DIN, nullptr, nullptr);
    reduce_part_kernel<<<(TOKS * XDBL + 255) / 256, 256>>>();

    convert_dtr_kernel<<<(TOKS * DTRANK) / 256, 256>>>();
    gemm_bf16<1><<<dim3(DIN / GBN, TOKS / GBM), 256>>>(
        edtr, 3 * DTRANK, ew3, 3 * DTRANK, dt, DIN, TOKS, DIN, 3 * DTRANK, dt_proj_b, nullptr);

    scan_kernel<<<(BB * DIN) / 16, 256>>>(A_log, Dvec);

    gemm_bf16<2><<<dim3(CC / GBN, TOKS / GBM), 256>>>(
        ey, 3 * DIN, ew4, 3 * DIN, out, 0, TOKS, CC, 3 * DIN, nullptr, x);
}

// round 4
// speedup vs baseline: 1.3460x; 1.0703x over previous
#include <cuda_runtime.h>
#include <cuda_bf16.h>
#include <math.h>
#include <stdint.h>

// ---------------- problem constants ----------------
#define BB      2
#define CC      1024
#define TT      1024
#define TOKS    (BB * TT)          // 2048
#define DIN     2048
#define DSTATE  16
#define DTRANK  64
#define XDBL    96
#define DCONV   4
#define SPLITK  16

// ---------------- fp32 scratch ----------------
__device__ float g_xz  [TOKS * 2 * DIN];
__device__ float g_xc  [TOKS * DIN];
__device__ float g_xdbl[TOKS * XDBL];
__device__ float g_dt  [TOKS * DIN];
__device__ float g_part[SPLITK * TOKS * XDBL];

// ---------------- bf16 split-precision scratch (A:[hi,hi,lo], W:[hi,lo,hi]) ----------------
__device__ __nv_bfloat16 e_xn [TOKS * 3 * CC];
__device__ __nv_bfloat16 e_w1 [2 * DIN * 3 * CC];
__device__ __nv_bfloat16 e_xc [TOKS * 3 * DIN];
__device__ __nv_bfloat16 e_w2 [XDBL * 3 * DIN];
__device__ __nv_bfloat16 e_dtr[TOKS * 3 * DTRANK];
__device__ __nv_bfloat16 e_w3 [DIN * 3 * DTRANK];
__device__ __nv_bfloat16 e_y  [TOKS * 3 * DIN];
__device__ __nv_bfloat16 e_w4 [CC * 3 * DIN];

__device__ __forceinline__ void split2(float v, __nv_bfloat16& hi, __nv_bfloat16& lo) {
    hi = __float2bfloat16(v);
    lo = __float2bfloat16(v - __bfloat162float(hi));
}

// ==================== PTX helpers ====================
__device__ __forceinline__ uint32_t smem_u32(const void* p) {
    uint32_t a;
    asm("{ .reg .u64 t; cvta.to.shared.u64 t, %1; cvt.u32.u64 %0, t; }" : "=r"(a) : "l"(p));
    return a;
}
__device__ __forceinline__ void cp16(uint32_t dst, const void* src, bool pred) {
    int sz = pred ? 16 : 0;
    asm volatile("cp.async.cg.shared.global [%0], [%1], 16, %2;\n" :: "r"(dst), "l"(src), "r"(sz));
}
__device__ __forceinline__ void ldsm4(uint32_t& r0, uint32_t& r1, uint32_t& r2, uint32_t& r3,
                                      uint32_t addr) {
    asm volatile("ldmatrix.sync.aligned.m8n8.x4.shared.b16 {%0,%1,%2,%3}, [%4];"
                 : "=r"(r0), "=r"(r1), "=r"(r2), "=r"(r3) : "r"(addr));
}
__device__ __forceinline__ void mma16816(float* c, const uint32_t* a, const uint32_t* b) {
    asm volatile("mma.sync.aligned.m16n8k16.row.col.f32.bf16.bf16.f32 "
                 "{%0,%1,%2,%3}, {%4,%5,%6,%7}, {%8,%9}, {%0,%1,%2,%3};"
                 : "+f"(c[0]), "+f"(c[1]), "+f"(c[2]), "+f"(c[3])
                 : "r"(a[0]), "r"(a[1]), "r"(a[2]), "r"(a[3]), "r"(b[0]), "r"(b[1]));
}

// ==================== mma.sync GEMM ====================
// C[M,N] = A[M,Kext] @ W[N,Kext]^T. Tile 128 x NT, K-tile 64, 3-stage cp.async ring.
// OP 0 plain | OP 1 softplus+bias | OP 2 transpose+residual | OP 3 split-K partials
template <int OP, int NT>
__global__ __launch_bounds__(256, 2)
void gemm_mma(const __nv_bfloat16* __restrict__ A, int lda,
              const __nv_bfloat16* __restrict__ W, int ldw,
              float* __restrict__ C, int ldc,
              int M, int N, int Kext,
              const float* __restrict__ bias,
              const float* __restrict__ resid) {
    constexpr int SA     = 128 * 128;       // A stage bytes (128 rows x 128B)
    constexpr int SB     = NT * 128;
    constexpr int STAGE  = SA + SB;
    constexpr int WCOLS  = NT / 2;          // cols per warp-half
    constexpr int NFR    = WCOLS / 8;       // B frags per warp
    constexpr int BLD    = WCOLS / 16;      // B ldmatrix.x4 per k16
    constexpr int BCHUNK = NT * 8 / 256;    // B cp16 per thread

    extern __shared__ float4 dyn4[];
    uint32_t base = smem_u32(dyn4);

    int tid = threadIdx.x, lane = tid & 31, warp = tid >> 5;
    int wm = warp & 3, wn = warp >> 2;
    int rowBase = blockIdx.y * 128, colBase = blockIdx.x * NT;

    int kStart = 0;
    if (OP == 3) {
        int ch = Kext / SPLITK;
        kStart = blockIdx.z * ch;
        Kext = ch;
        C += (size_t)blockIdx.z * M * ldc;
    }
    int nTiles = Kext / 64;

    float acc[2][NFR][4];
#pragma unroll
    for (int i = 0; i < 2; i++)
#pragma unroll
        for (int j = 0; j < NFR; j++)
#pragma unroll
            for (int e = 0; e < 4; e++) acc[i][j][e] = 0.f;

    auto load_tile = [&](int s, int kt) {
        uint32_t aB = base + s * STAGE, bB = aB + SA;
        int k0 = kStart + kt * 64;
#pragma unroll
        for (int i = 0; i < 4; i++) {                       // A: 1024 chunks
            int idx = tid + i * 256;
            int row = idx >> 3, c = idx & 7;
            cp16(aB + row * 128 + ((c ^ (row & 7)) << 4),
                 A + (size_t)(rowBase + row) * lda + k0 + c * 8, true);
        }
#pragma unroll
        for (int i = 0; i < BCHUNK; i++) {                  // B: NT*8 chunks
            int idx = tid + i * 256;
            int row = idx >> 3, c = idx & 7;
            bool ok = (colBase + row) < N;
            cp16(bB + row * 128 + ((c ^ (row & 7)) << 4),
                 W + (ok ? (size_t)(colBase + row) * ldw : 0) + k0 + c * 8, ok);
        }
        asm volatile("cp.async.commit_group;\n");
    };

    load_tile(0, 0);
    if (nTiles > 1) load_tile(1, 1);

    for (int t = 0; t < nTiles; t++) {
        if (t + 1 >= nTiles) asm volatile("cp.async.wait_group 0;\n");
        else                 asm volatile("cp.async.wait_group 1;\n");
        __syncthreads();

        int s = t % 3;
        uint32_t aB = base + s * STAGE, bB = aB + SA;
#pragma unroll
        for (int ks = 0; ks < 4; ks++) {
            uint32_t afr[2][4];
#pragma unroll
            for (int mt = 0; mt < 2; mt++) {
                int row = wm * 32 + mt * 16 + (lane & 15);
                int unit = ks * 2 + (lane >> 4);
                ldsm4(afr[mt][0], afr[mt][1], afr[mt][2], afr[mt][3],
                      aB + row * 128 + ((unit ^ (row & 7)) << 4));
            }
            uint32_t bfr[NFR][2];
#pragma unroll
            for (int p = 0; p < BLD; p++) {
                int row = wn * WCOLS + p * 16 + (lane & 15);
                int unit = ks * 2 + (lane >> 4);
                uint32_t r0, r1, r2, r3;
                ldsm4(r0, r1, r2, r3, bB + row * 128 + ((unit ^ (row & 7)) << 4));
                bfr[2 * p][0] = r0; bfr[2 * p + 1][0] = r1;
                bfr[2 * p][1] = r2; bfr[2 * p + 1][1] = r3;
            }
#pragma unroll
            for (int mt = 0; mt < 2; mt++)
#pragma unroll
                for (int nt = 0; nt < NFR; nt++)
                    mma16816(acc[mt][nt], afr[mt], bfr[nt]);
        }
        // prefetch t+2 into the retired stage; top-of-loop barrier makes this safe
        if (t + 2 < nTiles) load_tile((t + 2) % 3, t + 2);
    }

    // ---- epilogue ----
#pragma unroll
    for (int mt = 0; mt < 2; mt++) {
        int m = rowBase + wm * 32 + mt * 16 + (lane >> 2);
#pragma unroll
        for (int nt = 0; nt < NFR; nt++) {
            int c0 = colBase + wn * WCOLS + nt * 8 + (lane & 3) * 2;
#pragma unroll
            for (int e = 0; e < 4; e++) {
                int mm = m + ((e >= 2) ? 8 : 0);
                int n = c0 + (e & 1);
                if (OP != 2 && n >= N) continue;
                float v = acc[mt][nt][e];
                if (OP == 0 || OP == 3) {
                    C[(size_t)mm * ldc + n] = v;
                } else if (OP == 1) {
                    v += bias[n];
                    C[(size_t)mm * ldc + n] = (v > 20.f) ? v : log1pf(__expf(v));
                } else {
                    int b = mm >> 10, tt2 = mm & 1023;
                    size_t oi = (size_t)b * CC * TT + (size_t)n * TT + tt2;
                    C[oi] = v + resid[oi];
                }
            }
        }
    }
}

// ==================== elementwise kernels ====================
__global__ __launch_bounds__(256) void ln_kernel(const float* __restrict__ x,
                                                 const float* __restrict__ w,
                                                 const float* __restrict__ bvec) {
    int tok = blockIdx.x;
    int b = tok >> 10, t = tok & 1023;
    const float* xp = x + (size_t)b * CC * TT + t;

    float vals[4];
    float s = 0.f, s2 = 0.f;
#pragma unroll
    for (int i = 0; i < 4; i++) {
        int c = threadIdx.x + i * 256;
        float v = __ldg(xp + (size_t)c * TT);
        vals[i] = v;
        s += v;
        s2 = fmaf(v, v, s2);
    }
#pragma unroll
    for (int o = 16; o; o >>= 1) {
        s  += __shfl_xor_sync(0xffffffffu, s,  o);
        s2 += __shfl_xor_sync(0xffffffffu, s2, o);
    }
    __shared__ float sh[16];
    int wp = threadIdx.x >> 5, ln = threadIdx.x & 31;
    if (ln == 0) { sh[wp] = s; sh[8 + wp] = s2; }
    __syncthreads();
    float S = 0.f, S2 = 0.f;
#pragma unroll
    for (int i = 0; i < 8; i++) { S += sh[i]; S2 += sh[8 + i]; }
    float mu  = S * (1.f / 1024.f);
    float var = S2 * (1.f / 1024.f) - mu * mu;
    float rs  = rsqrtf(var + 1e-5f);

    __nv_bfloat16* op = e_xn + (size_t)tok * 3 * CC;
#pragma unroll
    for (int i = 0; i < 4; i++) {
        int c = threadIdx.x + i * 256;
        float v = (vals[i] - mu) * rs * w[c] + bvec[c];
        __nv_bfloat16 hi, lo; split2(v, hi, lo);
        op[c] = hi; op[CC + c] = hi; op[2 * CC + c] = lo;
    }
}

// vectorized ext conversion; MODE 0 weights [hi,lo,hi], MODE 1 acts [hi,hi,lo]
template <int MODE>
__global__ __launch_bounds__(256) void convert2_kernel(const float* __restrict__ in,
                                                       __nv_bfloat16* __restrict__ out,
                                                       int K, int halfTotal) {
    int i = blockIdx.x * 256 + threadIdx.x;
    if (i >= halfTotal) return;
    int K2 = K >> 1;
    int r = i / K2, k2 = i - r * K2;
    float2 v = *(const float2*)(in + (size_t)r * K + k2 * 2);
    __nv_bfloat16 h0, l0, h1, l1;
    split2(v.x, h0, l0); split2(v.y, h1, l1);
    uint32_t hh = ((uint32_t)__bfloat16_as_ushort(h1) << 16) | __bfloat16_as_ushort(h0);
    uint32_t ll = ((uint32_t)__bfloat16_as_ushort(l1) << 16) | __bfloat16_as_ushort(l0);
    uint32_t* o = (uint32_t*)(out + (size_t)r * 3 * K);
    if (MODE == 0) { o[k2] = hh; o[K2 + k2] = ll; o[K + k2] = hh; }
    else           { o[k2] = hh; o[K2 + k2] = hh; o[K + k2] = ll; }
}

__global__ __launch_bounds__(256) void convert_dtr2_kernel() {
    int i = blockIdx.x * 256 + threadIdx.x;       // TOKS*32
    int tok = i >> 5, k2 = i & 31;
    float2 v = *(const float2*)(g_xdbl + tok * XDBL + k2 * 2);
    __nv_bfloat16 h0, l0, h1, l1;
    split2(v.x, h0, l0); split2(v.y, h1, l1);
    uint32_t hh = ((uint32_t)__bfloat16_as_ushort(h1) << 16) | __bfloat16_as_ushort(h0);
    uint32_t ll = ((uint32_t)__bfloat16_as_ushort(l1) << 16) | __bfloat16_as_ushort(l0);
    uint32_t* o = (uint32_t*)(e_dtr + (size_t)tok * 3 * DTRANK);
    o[k2] = hh; o[32 + k2] = hh; o[64 + k2] = ll;
}

__global__ __launch_bounds__(256) void reduce_part_kernel() {
    int i = blockIdx.x * 256 + threadIdx.x;
    if (i >= TOKS * XDBL) return;
    float s = 0.f;
#pragma unroll
    for (int z = 0; z < SPLITK; z++) s += g_part[(size_t)z * TOKS * XDBL + i];
    g_xdbl[i] = s;
}

__global__ __launch_bounds__(256) void conv_silu_kernel(const float* __restrict__ conv_w,
                                                        const float* __restrict__ conv_b) {
    int idx = blockIdx.x * 256 + threadIdx.x;
    int d = idx & (DIN - 1);
    int tok = idx >> 11;
    int b = tok >> 10, t = tok & 1023;

    float w0 = conv_w[d * DCONV + 0];
    float w1 = conv_w[d * DCONV + 1];
    float w2 = conv_w[d * DCONV + 2];
    float w3 = conv_w[d * DCONV + 3];

    const float* xin = g_xz + (size_t)(b * TT) * (2 * DIN) + d;
    float v = conv_b[d];
    if (t >= 3) v = fmaf(w0, xin[(size_t)(t - 3) * (2 * DIN)], v);
    if (t >= 2) v = fmaf(w1, xin[(size_t)(t - 2) * (2 * DIN)], v);
    if (t >= 1) v = fmaf(w2, xin[(size_t)(t - 1) * (2 * DIN)], v);
    v = fmaf(w3, xin[(size_t)t * (2 * DIN)], v);

    float sig = 1.f / (1.f + __expf(-v));
    float o = v * sig;
    g_xc[idx] = o;
    __nv_bfloat16 hi, lo; split2(o, hi, lo);
    __nv_bfloat16* op = e_xc + (size_t)tok * 3 * DIN + d;
    op[0] = hi; op[DIN] = hi; op[2 * DIN] = lo;
}

__global__ __launch_bounds__(256) void scan_kernel(const float* __restrict__ A_log,
                                                   const float* __restrict__ Dvec) {
    int tid = threadIdx.x;
    int lane = tid & 31;
    int warp = tid >> 5;
    int s = lane & 15;
    int chInWarp = lane >> 4;
    int g = blockIdx.x * 16 + warp * 2 + chInWarp;
    int b = g >> 11;
    int d = g & (DIN - 1);

    float A_s = -__expf(A_log[d * DSTATE + s]);
    float Dd  = Dvec[d];

    const float* dtp = g_dt   + (size_t)(b * TT) * DIN + d;
    const float* xcp = g_xc   + (size_t)(b * TT) * DIN + d;
    const float* dbp = g_xdbl + (size_t)(b * TT) * XDBL;
    const float* zp  = g_xz   + (size_t)(b * TT) * (2 * DIN) + DIN + d;
    __nv_bfloat16* yp = e_y   + (size_t)(b * TT) * 3 * DIN + d;

    float h = 0.f;
    for (int t = 0; t < TT; t++) {
        float dtv = __ldg(dtp + (size_t)t * DIN);
        float xv  = __ldg(xcp + (size_t)t * DIN);
        float Bv  = __ldg(dbp + (size_t)t * XDBL + DTRANK + s);
        float Cv  = __ldg(dbp + (size_t)t * XDBL + DTRANK + DSTATE + s);

        float dA = __expf(dtv * A_s);
        h = fmaf(dA, h, dtv * Bv * xv);
        float p = h * Cv;
        p += __shfl_xor_sync(0xffffffffu, p, 8);
        p += __shfl_xor_sync(0xffffffffu, p, 4);
        p += __shfl_xor_sync(0xffffffffu, p, 2);
        p += __shfl_xor_sync(0xffffffffu, p, 1);
        if (s == 0) {
            float zv  = __ldg(zp + (size_t)t * (2 * DIN));
            float sig = 1.f / (1.f + __expf(-zv));
            float yv  = (p + Dd * xv) * (zv * sig);
            __nv_bfloat16 hi, lo; split2(yv, hi, lo);
            __nv_bfloat16* o = yp + (size_t)t * 3 * DIN;
            o[0] = hi; o[DIN] = hi; o[2 * DIN] = lo;
        }
    }
}

// ==================== launch ====================
extern "C" void kernel_launch(void* const* d_in, const int* in_sizes, int n_in,
                              void* d_out, int out_size) {
    const float* x          = (const float*)d_in[0];
    const float* norm_w     = (const float*)d_in[1];
    const float* norm_b     = (const float*)d_in[2];
    const float* in_proj_w  = (const float*)d_in[3];
    const float* conv_w     = (const float*)d_in[4];
    const float* conv_b     = (const float*)d_in[5];
    const float* x_proj_w   = (const float*)d_in[6];
    const float* dt_proj_w  = (const float*)d_in[7];
    const float* dt_proj_b  = (const float*)d_in[8];
    const float* A_log      = (const float*)d_in[9];
    const float* Dvec       = (const float*)d_in[10];
    const float* out_proj_w = (const float*)d_in[11];
    float* out = (float*)d_out;

    float *xz, *xdbl, *dt, *part;
    __nv_bfloat16 *exn, *ew1, *exc, *ew2, *edtr, *ew3, *ey, *ew4;
    cudaGetSymbolAddress((void**)&xz,   g_xz);
    cudaGetSymbolAddress((void**)&xdbl, g_xdbl);
    cudaGetSymbolAddress((void**)&dt,   g_dt);
    cudaGetSymbolAddress((void**)&part, g_part);
    cudaGetSymbolAddress((void**)&exn,  e_xn);
    cudaGetSymbolAddress((void**)&ew1,  e_w1);
    cudaGetSymbolAddress((void**)&exc,  e_xc);
    cudaGetSymbolAddress((void**)&ew2,  e_w2);
    cudaGetSymbolAddress((void**)&edtr, e_dtr);
    cudaGetSymbolAddress((void**)&ew3,  e_w3);
    cudaGetSymbolAddress((void**)&ey,   e_y);
    cudaGetSymbolAddress((void**)&ew4,  e_w4);

    const int smem128 = 3 * (128 * 128 + 128 * 128);   // 98304
    const int smem64  = 3 * (128 * 128 + 64 * 128);    // 73728
    cudaFuncSetAttribute(gemm_mma<0, 128>, cudaFuncAttributeMaxDynamicSharedMemorySize, smem128);
    cudaFuncSetAttribute(gemm_mma<1, 128>, cudaFuncAttributeMaxDynamicSharedMemorySize, smem128);
    cudaFuncSetAttribute(gemm_mma<3, 128>, cudaFuncAttributeMaxDynamicSharedMemorySize, smem128);
    cudaFuncSetAttribute(gemm_mma<2, 64>,  cudaFuncAttributeMaxDynamicSharedMemorySize, smem64);

    // 1. in_proj weight convert
    convert2_kernel<0><<<(2 * DIN * CC / 2 + 255) / 256, 256>>>(in_proj_w, ew1, CC, 2 * DIN * CC / 2);
    // 2. LayerNorm
    ln_kernel<<<TOKS, 256>>>(x, norm_w, norm_b);
    // 3. out_proj weight convert
    convert2_kernel<0><<<(CC * DIN / 2 + 255) / 256, 256>>>(out_proj_w, ew4, DIN, CC * DIN / 2);
    // 4. in_proj GEMM  (PROFILED LAUNCH)
    gemm_mma<0, 128><<<dim3((2 * DIN) / 128, TOKS / 128), 256, smem128>>>(
        exn, 3 * CC, ew1, 3 * CC, xz, 2 * DIN, TOKS, 2 * DIN, 3 * CC, nullptr, nullptr);
    // 5. conv + SiLU
    conv_silu_kernel<<<(TOKS * DIN) / 256, 256>>>(conv_w, conv_b);
    // 6. x_proj weight convert
    convert2_kernel<0><<<(XDBL * DIN / 2 + 255) / 256, 256>>>(x_proj_w, ew2, DIN, XDBL * DIN / 2);
    // 7. x_proj split-K GEMM
    gemm_mma<3, 128><<<dim3(1, TOKS / 128, SPLITK), 256, smem128>>>(
        exc, 3 * DIN, ew2, 3 * DIN, part, XDBL, TOKS, XDBL, 3 * DIN, nullptr, nullptr);
    // 8. reduce partials
    reduce_part_kernel<<<(TOKS * XDBL + 255) / 256, 256>>>();
    // 9. dt_raw convert
    convert_dtr2_kernel<<<(TOKS * 32) / 256, 256>>>();
    // 10. dt_proj weight convert
    convert2_kernel<0><<<(DIN * DTRANK / 2 + 255) / 256, 256>>>(dt_proj_w, ew3, DTRANK, DIN * DTRANK / 2);
    // 11. dt_proj + softplus
    gemm_mma<1, 128><<<dim3(DIN / 128, TOKS / 128), 256, smem128>>>(
        edtr, 3 * DTRANK, ew3, 3 * DTRANK, dt, DIN, TOKS, DIN, 3 * DTRANK, dt_proj_b, nullptr);
    // 12. selective scan + gate
    scan_kernel<<<(BB * DIN) / 16, 256>>>(A_log, Dvec);
    // 13. out_proj + residual transposed store
    gemm_mma<2, 64><<<dim3(CC / 64, TOKS / 128), 256, smem64>>>(
        ey, 3 * DIN, ew4, 3 * DIN, out, 0, TOKS, CC, 3 * DIN, nullptr, x);
}

// round 5
// speedup vs baseline: 3.9893x; 2.9637x over previous
#include <cuda_runtime.h>
#include <cuda_bf16.h>
#include <math.h>
#include <stdint.h>

// ---------------- problem constants ----------------
#define BB      2
#define CC      1024
#define TT      1024
#define TOKS    (BB * TT)          // 2048
#define DIN     2048
#define DSTATE  16
#define DTRANK  64
#define XDBL    96
#define DCONV   4
#define SPLITK  16
#define SW      64                 // scan window (t-steps)

// ---------------- fp32 scratch ----------------
__device__ float g_xz  [TOKS * 2 * DIN];
__device__ float g_xc  [TOKS * DIN];
__device__ float g_xdbl[TOKS * XDBL];
__device__ float g_dt  [TOKS * DIN];
__device__ float g_part[SPLITK * TOKS * XDBL];

// ---------------- bf16 split-precision scratch (A:[hi,hi,lo], W:[hi,lo,hi]) ----------------
__device__ __nv_bfloat16 e_xn [TOKS * 3 * CC];
__device__ __nv_bfloat16 e_w1 [2 * DIN * 3 * CC];
__device__ __nv_bfloat16 e_xc [TOKS * 3 * DIN];
__device__ __nv_bfloat16 e_w2 [XDBL * 3 * DIN];
__device__ __nv_bfloat16 e_dtr[TOKS * 3 * DTRANK];
__device__ __nv_bfloat16 e_w3 [DIN * 3 * DTRANK];
__device__ __nv_bfloat16 e_y  [TOKS * 3 * DIN];
__device__ __nv_bfloat16 e_w4 [CC * 3 * DIN];

__device__ __forceinline__ void split2(float v, __nv_bfloat16& hi, __nv_bfloat16& lo) {
    hi = __float2bfloat16(v);
    lo = __float2bfloat16(v - __bfloat162float(hi));
}

// ==================== PTX helpers ====================
__device__ __forceinline__ uint32_t smem_u32(const void* p) {
    uint32_t a;
    asm("{ .reg .u64 t; cvta.to.shared.u64 t, %1; cvt.u32.u64 %0, t; }" : "=r"(a) : "l"(p));
    return a;
}
__device__ __forceinline__ void cp16(uint32_t dst, const void* src, bool pred) {
    int sz = pred ? 16 : 0;
    asm volatile("cp.async.cg.shared.global [%0], [%1], 16, %2;\n" :: "r"(dst), "l"(src), "r"(sz));
}
__device__ __forceinline__ void ldsm4(uint32_t& r0, uint32_t& r1, uint32_t& r2, uint32_t& r3,
                                      uint32_t addr) {
    asm volatile("ldmatrix.sync.aligned.m8n8.x4.shared.b16 {%0,%1,%2,%3}, [%4];"
                 : "=r"(r0), "=r"(r1), "=r"(r2), "=r"(r3) : "r"(addr));
}
__device__ __forceinline__ void mma16816(float* c, const uint32_t* a, const uint32_t* b) {
    asm volatile("mma.sync.aligned.m16n8k16.row.col.f32.bf16.bf16.f32 "
                 "{%0,%1,%2,%3}, {%4,%5,%6,%7}, {%8,%9}, {%0,%1,%2,%3};"
                 : "+f"(c[0]), "+f"(c[1]), "+f"(c[2]), "+f"(c[3])
                 : "r"(a[0]), "r"(a[1]), "r"(a[2]), "r"(a[3]), "r"(b[0]), "r"(b[1]));
}

// ==================== mma.sync GEMM (unchanged from R4) ====================
template <int OP, int NT>
__global__ __launch_bounds__(256, 2)
void gemm_mma(const __nv_bfloat16* __restrict__ A, int lda,
              const __nv_bfloat16* __restrict__ W, int ldw,
              float* __restrict__ C, int ldc,
              int M, int N, int Kext,
              const float* __restrict__ bias,
              const float* __restrict__ resid) {
    constexpr int SA     = 128 * 128;
    constexpr int SB     = NT * 128;
    constexpr int STAGE  = SA + SB;
    constexpr int WCOLS  = NT / 2;
    constexpr int NFR    = WCOLS / 8;
    constexpr int BLD    = WCOLS / 16;
    constexpr int BCHUNK = NT * 8 / 256;

    extern __shared__ float4 dyn4[];
    uint32_t base = smem_u32(dyn4);

    int tid = threadIdx.x, lane = tid & 31, warp = tid >> 5;
    int wm = warp & 3, wn = warp >> 2;
    int rowBase = blockIdx.y * 128, colBase = blockIdx.x * NT;

    int kStart = 0;
    if (OP == 3) {
        int ch = Kext / SPLITK;
        kStart = blockIdx.z * ch;
        Kext = ch;
        C += (size_t)blockIdx.z * M * ldc;
    }
    int nTiles = Kext / 64;

    float acc[2][NFR][4];
#pragma unroll
    for (int i = 0; i < 2; i++)
#pragma unroll
        for (int j = 0; j < NFR; j++)
#pragma unroll
            for (int e = 0; e < 4; e++) acc[i][j][e] = 0.f;

    auto load_tile = [&](int s, int kt) {
        uint32_t aB = base + s * STAGE, bB = aB + SA;
        int k0 = kStart + kt * 64;
#pragma unroll
        for (int i = 0; i < 4; i++) {
            int idx = tid + i * 256;
            int row = idx >> 3, c = idx & 7;
            cp16(aB + row * 128 + ((c ^ (row & 7)) << 4),
                 A + (size_t)(rowBase + row) * lda + k0 + c * 8, true);
        }
#pragma unroll
        for (int i = 0; i < BCHUNK; i++) {
            int idx = tid + i * 256;
            int row = idx >> 3, c = idx & 7;
            bool ok = (colBase + row) < N;
            cp16(bB + row * 128 + ((c ^ (row & 7)) << 4),
                 W + (ok ? (size_t)(colBase + row) * ldw : 0) + k0 + c * 8, ok);
        }
        asm volatile("cp.async.commit_group;\n");
    };

    load_tile(0, 0);
    if (nTiles > 1) load_tile(1, 1);

    for (int t = 0; t < nTiles; t++) {
        if (t + 1 >= nTiles) asm volatile("cp.async.wait_group 0;\n");
        else                 asm volatile("cp.async.wait_group 1;\n");
        __syncthreads();

        int s = t % 3;
        uint32_t aB = base + s * STAGE, bB = aB + SA;
#pragma unroll
        for (int ks = 0; ks < 4; ks++) {
            uint32_t afr[2][4];
#pragma unroll
            for (int mt = 0; mt < 2; mt++) {
                int row = wm * 32 + mt * 16 + (lane & 15);
                int unit = ks * 2 + (lane >> 4);
                ldsm4(afr[mt][0], afr[mt][1], afr[mt][2], afr[mt][3],
                      aB + row * 128 + ((unit ^ (row & 7)) << 4));
            }
            uint32_t bfr[NFR][2];
#pragma unroll
            for (int p = 0; p < BLD; p++) {
                int row = wn * WCOLS + p * 16 + (lane & 15);
                int unit = ks * 2 + (lane >> 4);
                uint32_t r0, r1, r2, r3;
                ldsm4(r0, r1, r2, r3, bB + row * 128 + ((unit ^ (row & 7)) << 4));
                bfr[2 * p][0] = r0; bfr[2 * p + 1][0] = r1;
                bfr[2 * p][1] = r2; bfr[2 * p + 1][1] = r3;
            }
#pragma unroll
            for (int mt = 0; mt < 2; mt++)
#pragma unroll
                for (int nt = 0; nt < NFR; nt++)
                    mma16816(acc[mt][nt], afr[mt], bfr[nt]);
        }
        if (t + 2 < nTiles) load_tile((t + 2) % 3, t + 2);
    }

#pragma unroll
    for (int mt = 0; mt < 2; mt++) {
        int m = rowBase + wm * 32 + mt * 16 + (lane >> 2);
#pragma unroll
        for (int nt = 0; nt < NFR; nt++) {
            int c0 = colBase + wn * WCOLS + nt * 8 + (lane & 3) * 2;
#pragma unroll
            for (int e = 0; e < 4; e++) {
                int mm = m + ((e >= 2) ? 8 : 0);
                int n = c0 + (e & 1);
                if (OP != 2 && n >= N) continue;
                float v = acc[mt][nt][e];
                if (OP == 0 || OP == 3) {
                    C[(size_t)mm * ldc + n] = v;
                } else if (OP == 1) {
                    v += bias[n];
                    C[(size_t)mm * ldc + n] = (v > 20.f) ? v : log1pf(__expf(v));
                } else {
                    int b = mm >> 10, tt2 = mm & 1023;
                    size_t oi = (size_t)b * CC * TT + (size_t)n * TT + tt2;
                    C[oi] = v + resid[oi];
                }
            }
        }
    }
}

// ==================== elementwise kernels ====================
__global__ __launch_bounds__(256) void ln_kernel(const float* __restrict__ x,
                                                 const float* __restrict__ w,
                                                 const float* __restrict__ bvec) {
    int tok = blockIdx.x;
    int b = tok >> 10, t = tok & 1023;
    const float* xp = x + (size_t)b * CC * TT + t;

    float vals[4];
    float s = 0.f, s2 = 0.f;
#pragma unroll
    for (int i = 0; i < 4; i++) {
        int c = threadIdx.x + i * 256;
        float v = __ldg(xp + (size_t)c * TT);
        vals[i] = v;
        s += v;
        s2 = fmaf(v, v, s2);
    }
#pragma unroll
    for (int o = 16; o; o >>= 1) {
        s  += __shfl_xor_sync(0xffffffffu, s,  o);
        s2 += __shfl_xor_sync(0xffffffffu, s2, o);
    }
    __shared__ float sh[16];
    int wp = threadIdx.x >> 5, ln = threadIdx.x & 31;
    if (ln == 0) { sh[wp] = s; sh[8 + wp] = s2; }
    __syncthreads();
    float S = 0.f, S2 = 0.f;
#pragma unroll
    for (int i = 0; i < 8; i++) { S += sh[i]; S2 += sh[8 + i]; }
    float mu  = S * (1.f / 1024.f);
    float var = S2 * (1.f / 1024.f) - mu * mu;
    float rs  = rsqrtf(var + 1e-5f);

    __nv_bfloat16* op = e_xn + (size_t)tok * 3 * CC;
#pragma unroll
    for (int i = 0; i < 4; i++) {
        int c = threadIdx.x + i * 256;
        float v = (vals[i] - mu) * rs * w[c] + bvec[c];
        __nv_bfloat16 hi, lo; split2(v, hi, lo);
        op[c] = hi; op[CC + c] = hi; op[2 * CC + c] = lo;
    }
}

template <int MODE>
__global__ __launch_bounds__(256) void convert2_kernel(const float* __restrict__ in,
                                                       __nv_bfloat16* __restrict__ out,
                                                       int K, int halfTotal) {
    int i = blockIdx.x * 256 + threadIdx.x;
    if (i >= halfTotal) return;
    int K2 = K >> 1;
    int r = i / K2, k2 = i - r * K2;
    float2 v = *(const float2*)(in + (size_t)r * K + k2 * 2);
    __nv_bfloat16 h0, l0, h1, l1;
    split2(v.x, h0, l0); split2(v.y, h1, l1);
    uint32_t hh = ((uint32_t)__bfloat16_as_ushort(h1) << 16) | __bfloat16_as_ushort(h0);
    uint32_t ll = ((uint32_t)__bfloat16_as_ushort(l1) << 16) | __bfloat16_as_ushort(l0);
    uint32_t* o = (uint32_t*)(out + (size_t)r * 3 * K);
    if (MODE == 0) { o[k2] = hh; o[K2 + k2] = ll; o[K + k2] = hh; }
    else           { o[k2] = hh; o[K2 + k2] = hh; o[K + k2] = ll; }
}

__global__ __launch_bounds__(256) void convert_dtr2_kernel() {
    int i = blockIdx.x * 256 + threadIdx.x;
    int tok = i >> 5, k2 = i & 31;
    float2 v = *(const float2*)(g_xdbl + tok * XDBL + k2 * 2);
    __nv_bfloat16 h0, l0, h1, l1;
    split2(v.x, h0, l0); split2(v.y, h1, l1);
    uint32_t hh = ((uint32_t)__bfloat16_as_ushort(h1) << 16) | __bfloat16_as_ushort(h0);
    uint32_t ll = ((uint32_t)__bfloat16_as_ushort(l1) << 16) | __bfloat16_as_ushort(l0);
    uint32_t* o = (uint32_t*)(e_dtr + (size_t)tok * 3 * DTRANK);
    o[k2] = hh; o[32 + k2] = hh; o[64 + k2] = ll;
}

__global__ __launch_bounds__(256) void reduce_part_kernel() {
    int i = blockIdx.x * 256 + threadIdx.x;
    if (i >= TOKS * XDBL) return;
    float s = 0.f;
#pragma unroll
    for (int z = 0; z < SPLITK; z++) s += g_part[(size_t)z * TOKS * XDBL + i];
    g_xdbl[i] = s;
}

__global__ __launch_bounds__(256) void conv_silu_kernel(const float* __restrict__ conv_w,
                                                        const float* __restrict__ conv_b) {
    int idx = blockIdx.x * 256 + threadIdx.x;
    int d = idx & (DIN - 1);
    int tok = idx >> 11;
    int b = tok >> 10, t = tok & 1023;

    float w0 = conv_w[d * DCONV + 0];
    float w1 = conv_w[d * DCONV + 1];
    float w2 = conv_w[d * DCONV + 2];
    float w3 = conv_w[d * DCONV + 3];

    const float* xin = g_xz + (size_t)(b * TT) * (2 * DIN) + d;
    float v = conv_b[d];
    if (t >= 3) v = fmaf(w0, xin[(size_t)(t - 3) * (2 * DIN)], v);
    if (t >= 2) v = fmaf(w1, xin[(size_t)(t - 2) * (2 * DIN)], v);
    if (t >= 1) v = fmaf(w2, xin[(size_t)(t - 1) * (2 * DIN)], v);
    v = fmaf(w3, xin[(size_t)t * (2 * DIN)], v);

    float sig = 1.f / (1.f + __expf(-v));
    float o = v * sig;
    g_xc[idx] = o;
    __nv_bfloat16 hi, lo; split2(o, hi, lo);
    __nv_bfloat16* op = e_xc + (size_t)tok * 3 * DIN + d;
    op[0] = hi; op[DIN] = hi; op[2 * DIN] = lo;
}

// ==================== windowed smem selective scan ====================
// block = 32 channels (one b), 512 threads = 16 warps (2 ch/warp, lane=state).
// T split into 16 windows of SW=64; dt/xc/z/(B|C) staged via double-buffered cp.async;
// y staged in smem and written back coalesced with the silu(z) gate fused.
__global__ __launch_bounds__(512) void scan_kernel(const float* __restrict__ A_log,
                                                   const float* __restrict__ Dvec) {
    __shared__ __align__(16) float s_buf[2][4][SW * 32];  // [buf][dt,xc,z,bc][t*32+..]
    __shared__ float s_y[SW][32];

    int tid  = threadIdx.x;
    int lane = tid & 31, warp = tid >> 5;
    int chBase = blockIdx.x * 32;
    int b  = chBase >> 11;
    int d0 = chBase & (DIN - 1);
    int s  = lane & 15;
    int dloc = warp * 2 + (lane >> 4);
    int d = d0 + dloc;

    float A_s = -__expf(A_log[d * DSTATE + s]);
    float Dd  = Dvec[d];

    const float* dtG = g_dt   + (size_t)(b * TT) * DIN + d0;
    const float* xcG = g_xc   + (size_t)(b * TT) * DIN + d0;
    const float* zG  = g_xz   + (size_t)(b * TT) * (2 * DIN) + DIN + d0;
    const float* bcG = g_xdbl + (size_t)(b * TT) * XDBL + DTRANK;

    int lt  = tid >> 3;          // 0..63 window row handled by this thread for loads
    int seg = tid & 7;           // 16B segment within the 128B row

    auto load_win = [&](int w, int buf) {
        int t0 = w * SW;
        const float* srcs[4] = {
            dtG + (size_t)(t0 + lt) * DIN       + seg * 4,
            xcG + (size_t)(t0 + lt) * DIN       + seg * 4,
            zG  + (size_t)(t0 + lt) * (2 * DIN) + seg * 4,
            bcG + (size_t)(t0 + lt) * XDBL      + seg * 4 };
#pragma unroll
        for (int a = 0; a < 4; a++)
            cp16(smem_u32(&s_buf[buf][a][lt * 32 + seg * 4]), srcs[a], true);
        asm volatile("cp.async.commit_group;\n");
    };

    constexpr int NW = TT / SW;
    load_win(0, 0);
    int buf = 0;
    float h = 0.f;

    for (int w = 0; w < NW; w++) {
        if (w + 1 < NW) {
            load_win(w + 1, buf ^ 1);
            asm volatile("cp.async.wait_group 1;\n");
        } else {
            asm volatile("cp.async.wait_group 0;\n");
        }
        __syncthreads();

        const float* fDT = s_buf[buf][0];
        const float* fXC = s_buf[buf][1];
        const float* fBC = s_buf[buf][3];
#pragma unroll 4
        for (int t = 0; t < SW; t++) {
            float dtv = fDT[t * 32 + dloc];
            float xv  = fXC[t * 32 + dloc];
            float Bv  = fBC[t * 32 + s];
            float Cv  = fBC[t * 32 + 16 + s];
            float dA  = __expf(dtv * A_s);
            h = fmaf(dA, h, dtv * Bv * xv);
            float p = h * Cv;
            p += __shfl_xor_sync(0xffffffffu, p, 8);
            p += __shfl_xor_sync(0xffffffffu, p, 4);
            p += __shfl_xor_sync(0xffffffffu, p, 2);
            p += __shfl_xor_sync(0xffffffffu, p, 1);
            if (s == 0) s_y[t][dloc] = fmaf(Dd, xv, p);
        }
        __syncthreads();

        // coalesced gated writeback of this window
        const float* fZ = s_buf[buf][2];
        int t0 = w * SW;
#pragma unroll
        for (int k = 0; k < 4; k++) {
            int idx = tid + k * 512;            // 2048 = 64t x 32d
            int t = idx >> 5, dd = idx & 31;
            float yv = s_y[t][dd];
            float zv = fZ[t * 32 + dd];
            float sig = 1.f / (1.f + __expf(-zv));
            yv *= zv * sig;
            __nv_bfloat16 hi, lo; split2(yv, hi, lo);
            __nv_bfloat16* o = e_y + (size_t)(b * TT + t0 + t) * 3 * DIN + d0 + dd;
            o[0] = hi; o[DIN] = hi; o[2 * DIN] = lo;
        }
        __syncthreads();   // protect buf^1 (z/s_y) before next window's cp.async
        buf ^= 1;
    }
}

// ==================== launch ====================
extern "C" void kernel_launch(void* const* d_in, const int* in_sizes, int n_in,
                              void* d_out, int out_size) {
    const float* x          = (const float*)d_in[0];
    const float* norm_w     = (const float*)d_in[1];
    const float* norm_b     = (const float*)d_in[2];
    const float* in_proj_w  = (const float*)d_in[3];
    const float* conv_w     = (const float*)d_in[4];
    const float* conv_b     = (const float*)d_in[5];
    const float* x_proj_w   = (const float*)d_in[6];
    const float* dt_proj_w  = (const float*)d_in[7];
    const float* dt_proj_b  = (const float*)d_in[8];
    const float* A_log      = (const float*)d_in[9];
    const float* Dvec       = (const float*)d_in[10];
    const float* out_proj_w = (const float*)d_in[11];
    float* out = (float*)d_out;

    float *xz, *xdbl, *dt, *part;
    __nv_bfloat16 *exn, *ew1, *exc, *ew2, *edtr, *ew3, *ey, *ew4;
    cudaGetSymbolAddress((void**)&xz,   g_xz);
    cudaGetSymbolAddress((void**)&xdbl, g_xdbl);
    cudaGetSymbolAddress((void**)&dt,   g_dt);
    cudaGetSymbolAddress((void**)&part, g_part);
    cudaGetSymbolAddress((void**)&exn,  e_xn);
    cudaGetSymbolAddress((void**)&ew1,  e_w1);
    cudaGetSymbolAddress((void**)&exc,  e_xc);
    cudaGetSymbolAddress((void**)&ew2,  e_w2);
    cudaGetSymbolAddress((void**)&edtr, e_dtr);
    cudaGetSymbolAddress((void**)&ew3,  e_w3);
    cudaGetSymbolAddress((void**)&ey,   e_y);
    cudaGetSymbolAddress((void**)&ew4,  e_w4);

    const int smem128 = 3 * (128 * 128 + 128 * 128);   // 98304
    const int smem64  = 3 * (128 * 128 + 64 * 128);    // 73728
    cudaFuncSetAttribute(gemm_mma<0, 128>, cudaFuncAttributeMaxDynamicSharedMemorySize, smem128);
    cudaFuncSetAttribute(gemm_mma<1, 128>, cudaFuncAttributeMaxDynamicSharedMemorySize, smem128);
    cudaFuncSetAttribute(gemm_mma<3, 128>, cudaFuncAttributeMaxDynamicSharedMemorySize, smem128);
    cudaFuncSetAttribute(gemm_mma<2, 64>,  cudaFuncAttributeMaxDynamicSharedMemorySize, smem64);

    // 1. in_proj weight convert
    convert2_kernel<0><<<(2 * DIN * CC / 2 + 255) / 256, 256>>>(in_proj_w, ew1, CC, 2 * DIN * CC / 2);
    // 2. LayerNorm
    ln_kernel<<<TOKS, 256>>>(x, norm_w, norm_b);
    // 3. out_proj weight convert
    convert2_kernel<0><<<(CC * DIN / 2 + 255) / 256, 256>>>(out_proj_w, ew4, DIN, CC * DIN / 2);
    // 4. in_proj GEMM  (PROFILED LAUNCH)
    gemm_mma<0, 128><<<dim3((2 * DIN) / 128, TOKS / 128), 256, smem128>>>(
        exn, 3 * CC, ew1, 3 * CC, xz, 2 * DIN, TOKS, 2 * DIN, 3 * CC, nullptr, nullptr);
    // 5. conv + SiLU
    conv_silu_kernel<<<(TOKS * DIN) / 256, 256>>>(conv_w, conv_b);
    // 6. x_proj weight convert
    convert2_kernel<0><<<(XDBL * DIN / 2 + 255) / 256, 256>>>(x_proj_w, ew2, DIN, XDBL * DIN / 2);
    // 7. x_proj split-K GEMM
    gemm_mma<3, 128><<<dim3(1, TOKS / 128, SPLITK), 256, smem128>>>(
        exc, 3 * DIN, ew2, 3 * DIN, part, XDBL, TOKS, XDBL, 3 * DIN, nullptr, nullptr);
    // 8. reduce partials
    reduce_part_kernel<<<(TOKS * XDBL + 255) / 256, 256>>>();
    // 9. dt_raw convert
    convert_dtr2_kernel<<<(TOKS * 32) / 256, 256>>>();
    // 10. dt_proj weight convert
    convert2_kernel<0><<<(DIN * DTRANK / 2 + 255) / 256, 256>>>(dt_proj_w, ew3, DTRANK, DIN * DTRANK / 2);
    // 11. dt_proj + softplus
    gemm_mma<1, 128><<<dim3(DIN / 128, TOKS / 128), 256, smem128>>>(
        edtr, 3 * DTRANK, ew3, 3 * DTRANK, dt, DIN, TOKS, DIN, 3 * DTRANK, dt_proj_b, nullptr);
    // 12. selective scan + gate (windowed smem pipeline)
    scan_kernel<<<(BB * DIN) / 32, 512>>>(A_log, Dvec);
    // 13. out_proj + residual transposed store
    gemm_mma<2, 64><<<dim3(CC / 64, TOKS / 128), 256, smem64>>>(
        ey, 3 * DIN, ew4, 3 * DIN, out, 0, TOKS, CC, 3 * DIN, nullptr, x);
}

// round 6
// speedup vs baseline: 4.8467x; 1.2149x over previous
#include <cuda_runtime.h>
#include <cuda_fp16.h>
#include <math.h>
#include <stdint.h>

// ---------------- problem constants ----------------
#define BB      2
#define CC      1024
#define TT      1024
#define TOKS    (BB * TT)          // 2048
#define DIN     2048
#define DSTATE  16
#define DTRANK  64
#define XDBL    96
#define DCONV   4
#define SPLITK  16
#define SW      64                 // scan window (t-steps)

// ---------------- fp32 scratch ----------------
__device__ float g_xz  [TOKS * 2 * DIN];
__device__ float g_xc  [TOKS * DIN];
__device__ float g_xdbl[TOKS * XDBL];
__device__ float g_dt  [TOKS * DIN];
__device__ float g_part[SPLITK * TOKS * XDBL];

// ---------------- fp16 2-term split scratch (acts:[hi,lo], weights:[hi,hi]) ----------------
__device__ __half e_xn [TOKS * 2 * CC];
__device__ __half e_w1 [2 * DIN * 2 * CC];
__device__ __half e_xc [TOKS * 2 * DIN];
__device__ __half e_w2 [XDBL * 2 * DIN];
__device__ __half e_dtr[TOKS * 2 * DTRANK];
__device__ __half e_w3 [DIN * 2 * DTRANK];
__device__ __half e_y  [TOKS * 2 * DIN];
__device__ __half e_w4 [CC * 2 * DIN];

__device__ __forceinline__ void split2h(float v, __half& hi, __half& lo) {
    hi = __float2half_rn(v);
    lo = __float2half_rn(v - __half2float(hi));
}

// ==================== PTX helpers ====================
__device__ __forceinline__ uint32_t smem_u32(const void* p) {
    uint32_t a;
    asm("{ .reg .u64 t; cvta.to.shared.u64 t, %1; cvt.u32.u64 %0, t; }" : "=r"(a) : "l"(p));
    return a;
}
__device__ __forceinline__ void cp16(uint32_t dst, const void* src, bool pred) {
    int sz = pred ? 16 : 0;
    asm volatile("cp.async.cg.shared.global [%0], [%1], 16, %2;\n" :: "r"(dst), "l"(src), "r"(sz));
}
__device__ __forceinline__ void ldsm4(uint32_t& r0, uint32_t& r1, uint32_t& r2, uint32_t& r3,
                                      uint32_t addr) {
    asm volatile("ldmatrix.sync.aligned.m8n8.x4.shared.b16 {%0,%1,%2,%3}, [%4];"
                 : "=r"(r0), "=r"(r1), "=r"(r2), "=r"(r3) : "r"(addr));
}
__device__ __forceinline__ void mma16816(float* c, const uint32_t* a, const uint32_t* b) {
    asm volatile("mma.sync.aligned.m16n8k16.row.col.f32.f16.f16.f32 "
                 "{%0,%1,%2,%3}, {%4,%5,%6,%7}, {%8,%9}, {%0,%1,%2,%3};"
                 : "+f"(c[0]), "+f"(c[1]), "+f"(c[2]), "+f"(c[3])
                 : "r"(a[0]), "r"(a[1]), "r"(a[2]), "r"(a[3]), "r"(b[0]), "r"(b[1]));
}

// ==================== mma.sync fp16 GEMM ====================
// C[M,N] = A[M,Kext] @ W[N,Kext]^T. Tile 128 x NT, K-tile 64, 3-stage cp.async ring.
// OP 0 plain | OP 1 softplus+bias | OP 2 transpose+residual | OP 3 split-K partials
template <int OP, int NT>
__global__ __launch_bounds__(256, 2)
void gemm_mma(const __half* __restrict__ A, int lda,
              const __half* __restrict__ W, int ldw,
              float* __restrict__ C, int ldc,
              int M, int N, int Kext,
              const float* __restrict__ bias,
              const float* __restrict__ resid) {
    constexpr int SA     = 128 * 128;
    constexpr int SB     = NT * 128;
    constexpr int STAGE  = SA + SB;
    constexpr int WCOLS  = NT / 2;
    constexpr int NFR    = WCOLS / 8;
    constexpr int BLD    = WCOLS / 16;
    constexpr int BCHUNK = NT * 8 / 256;

    extern __shared__ float4 dyn4[];
    uint32_t base = smem_u32(dyn4);

    int tid = threadIdx.x, lane = tid & 31, warp = tid >> 5;
    int wm = warp & 3, wn = warp >> 2;
    int rowBase = blockIdx.y * 128, colBase = blockIdx.x * NT;

    int kStart = 0;
    if (OP == 3) {
        int ch = Kext / SPLITK;
        kStart = blockIdx.z * ch;
        Kext = ch;
        C += (size_t)blockIdx.z * M * ldc;
    }
    int nTiles = Kext / 64;

    float acc[2][NFR][4];
#pragma unroll
    for (int i = 0; i < 2; i++)
#pragma unroll
        for (int j = 0; j < NFR; j++)
#pragma unroll
            for (int e = 0; e < 4; e++) acc[i][j][e] = 0.f;

    auto load_tile = [&](int s, int kt) {
        uint32_t aB = base + s * STAGE, bB = aB + SA;
        int k0 = kStart + kt * 64;
#pragma unroll
        for (int i = 0; i < 4; i++) {
            int idx = tid + i * 256;
            int row = idx >> 3, c = idx & 7;
            cp16(aB + row * 128 + ((c ^ (row & 7)) << 4),
                 A + (size_t)(rowBase + row) * lda + k0 + c * 8, true);
        }
#pragma unroll
        for (int i = 0; i < BCHUNK; i++) {
            int idx = tid + i * 256;
            int row = idx >> 3, c = idx & 7;
            bool ok = (colBase + row) < N;
            cp16(bB + row * 128 + ((c ^ (row & 7)) << 4),
                 W + (ok ? (size_t)(colBase + row) * ldw : 0) + k0 + c * 8, ok);
        }
        asm volatile("cp.async.commit_group;\n");
    };

    load_tile(0, 0);
    if (nTiles > 1) load_tile(1, 1);

    for (int t = 0; t < nTiles; t++) {
        if (t + 1 >= nTiles) asm volatile("cp.async.wait_group 0;\n");
        else                 asm volatile("cp.async.wait_group 1;\n");
        __syncthreads();

        int s = t % 3;
        uint32_t aB = base + s * STAGE, bB = aB + SA;
#pragma unroll
        for (int ks = 0; ks < 4; ks++) {
            uint32_t afr[2][4];
#pragma unroll
            for (int mt = 0; mt < 2; mt++) {
                int row = wm * 32 + mt * 16 + (lane & 15);
                int unit = ks * 2 + (lane >> 4);
                ldsm4(afr[mt][0], afr[mt][1], afr[mt][2], afr[mt][3],
                      aB + row * 128 + ((unit ^ (row & 7)) << 4));
            }
            uint32_t bfr[NFR][2];
#pragma unroll
            for (int p = 0; p < BLD; p++) {
                int row = wn * WCOLS + p * 16 + (lane & 15);
                int unit = ks * 2 + (lane >> 4);
                uint32_t r0, r1, r2, r3;
                ldsm4(r0, r1, r2, r3, bB + row * 128 + ((unit ^ (row & 7)) << 4));
                bfr[2 * p][0] = r0; bfr[2 * p + 1][0] = r1;
                bfr[2 * p][1] = r2; bfr[2 * p + 1][1] = r3;
            }
#pragma unroll
            for (int mt = 0; mt < 2; mt++)
#pragma unroll
                for (int nt = 0; nt < NFR; nt++)
                    mma16816(acc[mt][nt], afr[mt], bfr[nt]);
        }
        if (t + 2 < nTiles) load_tile((t + 2) % 3, t + 2);
    }

#pragma unroll
    for (int mt = 0; mt < 2; mt++) {
        int m = rowBase + wm * 32 + mt * 16 + (lane >> 2);
#pragma unroll
        for (int nt = 0; nt < NFR; nt++) {
            int c0 = colBase + wn * WCOLS + nt * 8 + (lane & 3) * 2;
#pragma unroll
            for (int e = 0; e < 4; e++) {
                int mm = m + ((e >= 2) ? 8 : 0);
                int n = c0 + (e & 1);
                if (OP != 2 && n >= N) continue;
                float v = acc[mt][nt][e];
                if (OP == 0 || OP == 3) {
                    C[(size_t)mm * ldc + n] = v;
                } else if (OP == 1) {
                    v += bias[n];
                    C[(size_t)mm * ldc + n] = (v > 20.f) ? v : log1pf(__expf(v));
                } else {
                    int b = mm >> 10, tt2 = mm & 1023;
                    size_t oi = (size_t)b * CC * TT + (size_t)n * TT + tt2;
                    C[oi] = v + resid[oi];
                }
            }
        }
    }
}

// ==================== elementwise kernels ====================
__global__ __launch_bounds__(256) void ln_kernel(const float* __restrict__ x,
                                                 const float* __restrict__ w,
                                                 const float* __restrict__ bvec) {
    int tok = blockIdx.x;
    int b = tok >> 10, t = tok & 1023;
    const float* xp = x + (size_t)b * CC * TT + t;

    float vals[4];
    float s = 0.f, s2 = 0.f;
#pragma unroll
    for (int i = 0; i < 4; i++) {
        int c = threadIdx.x + i * 256;
        float v = __ldg(xp + (size_t)c * TT);
        vals[i] = v;
        s += v;
        s2 = fmaf(v, v, s2);
    }
#pragma unroll
    for (int o = 16; o; o >>= 1) {
        s  += __shfl_xor_sync(0xffffffffu, s,  o);
        s2 += __shfl_xor_sync(0xffffffffu, s2, o);
    }
    __shared__ float sh[16];
    int wp = threadIdx.x >> 5, ln = threadIdx.x & 31;
    if (ln == 0) { sh[wp] = s; sh[8 + wp] = s2; }
    __syncthreads();
    float S = 0.f, S2 = 0.f;
#pragma unroll
    for (int i = 0; i < 8; i++) { S += sh[i]; S2 += sh[8 + i]; }
    float mu  = S * (1.f / 1024.f);
    float var = S2 * (1.f / 1024.f) - mu * mu;
    float rs  = rsqrtf(var + 1e-5f);

    __half* op = e_xn + (size_t)tok * 2 * CC;
#pragma unroll
    for (int i = 0; i < 4; i++) {
        int c = threadIdx.x + i * 256;
        float v = (vals[i] - mu) * rs * w[c] + bvec[c];
        __half hi, lo; split2h(v, hi, lo);
        op[c] = hi; op[CC + c] = lo;
    }
}

// vectorized ext conversion; MODE 0 weights [hi,hi], MODE 1 acts [hi,lo]
template <int MODE>
__global__ __launch_bounds__(256) void convert2_kernel(const float* __restrict__ in,
                                                       __half* __restrict__ out,
                                                       int K, int halfTotal) {
    int i = blockIdx.x * 256 + threadIdx.x;
    if (i >= halfTotal) return;
    int K2 = K >> 1;
    int r = i / K2, k2 = i - r * K2;
    float2 v = *(const float2*)(in + (size_t)r * K + k2 * 2);
    __half h0, l0, h1, l1;
    split2h(v.x, h0, l0); split2h(v.y, h1, l1);
    uint32_t hh = ((uint32_t)__half_as_ushort(h1) << 16) | __half_as_ushort(h0);
    uint32_t ll = ((uint32_t)__half_as_ushort(l1) << 16) | __half_as_ushort(l0);
    uint32_t* o = (uint32_t*)(out + (size_t)r * 2 * K);
    if (MODE == 0) { o[k2] = hh; o[K2 + k2] = hh; }
    else           { o[k2] = hh; o[K2 + k2] = ll; }
}

// split-K reduce + fused dt_raw ext conversion
__global__ __launch_bounds__(256) void reduce_part_kernel() {
    int i = blockIdx.x * 256 + threadIdx.x;
    if (i >= TOKS * XDBL) return;
    float s = 0.f;
#pragma unroll
    for (int z = 0; z < SPLITK; z++) s += g_part[(size_t)z * TOKS * XDBL + i];
    g_xdbl[i] = s;
    int tok = i / XDBL, k = i - tok * XDBL;
    if (k < DTRANK) {
        __half hi, lo; split2h(s, hi, lo);
        __half* o = e_dtr + (size_t)tok * 2 * DTRANK;
        o[k] = hi; o[DTRANK + k] = lo;
    }
}

__global__ __launch_bounds__(256) void conv_silu_kernel(const float* __restrict__ conv_w,
                                                        const float* __restrict__ conv_b) {
    int idx = blockIdx.x * 256 + threadIdx.x;
    int d = idx & (DIN - 1);
    int tok = idx >> 11;
    int b = tok >> 10, t = tok & 1023;

    float w0 = conv_w[d * DCONV + 0];
    float w1 = conv_w[d * DCONV + 1];
    float w2 = conv_w[d * DCONV + 2];
    float w3 = conv_w[d * DCONV + 3];

    const float* xin = g_xz + (size_t)(b * TT) * (2 * DIN) + d;
    float v = conv_b[d];
    if (t >= 3) v = fmaf(w0, xin[(size_t)(t - 3) * (2 * DIN)], v);
    if (t >= 2) v = fmaf(w1, xin[(size_t)(t - 2) * (2 * DIN)], v);
    if (t >= 1) v = fmaf(w2, xin[(size_t)(t - 1) * (2 * DIN)], v);
    v = fmaf(w3, xin[(size_t)t * (2 * DIN)], v);

    float sig = 1.f / (1.f + __expf(-v));
    float o = v * sig;
    g_xc[idx] = o;
    __half hi, lo; split2h(o, hi, lo);
    __half* op = e_xc + (size_t)tok * 2 * DIN + d;
    op[0] = hi; op[DIN] = lo;
}

// ==================== windowed smem selective scan ====================
__global__ __launch_bounds__(512) void scan_kernel(const float* __restrict__ A_log,
                                                   const float* __restrict__ Dvec) {
    __shared__ __align__(16) float s_buf[2][4][SW * 32];  // [buf][dt,xc,z,bc]
    __shared__ float s_y[SW][32];

    int tid  = threadIdx.x;
    int lane = tid & 31, warp = tid >> 5;
    int chBase = blockIdx.x * 32;
    int b  = chBase >> 11;
    int d0 = chBase & (DIN - 1);
    int s  = lane & 15;
    int dloc = warp * 2 + (lane >> 4);
    int d = d0 + dloc;

    float A_s = -__expf(A_log[d * DSTATE + s]);
    float Dd  = Dvec[d];

    const float* dtG = g_dt   + (size_t)(b * TT) * DIN + d0;
    const float* xcG = g_xc   + (size_t)(b * TT) * DIN + d0;
    const float* zG  = g_xz   + (size_t)(b * TT) * (2 * DIN) + DIN + d0;
    const float* bcG = g_xdbl + (size_t)(b * TT) * XDBL + DTRANK;

    int lt  = tid >> 3;
    int seg = tid & 7;

    auto load_win = [&](int w, int buf) {
        int t0 = w * SW;
        const float* srcs[4] = {
            dtG + (size_t)(t0 + lt) * DIN       + seg * 4,
            xcG + (size_t)(t0 + lt) * DIN       + seg * 4,
            zG  + (size_t)(t0 + lt) * (2 * DIN) + seg * 4,
            bcG + (size_t)(t0 + lt) * XDBL      + seg * 4 };
#pragma unroll
        for (int a = 0; a < 4; a++)
            cp16(smem_u32(&s_buf[buf][a][lt * 32 + seg * 4]), srcs[a], true);
        asm volatile("cp.async.commit_group;\n");
    };

    constexpr int NW = TT / SW;
    load_win(0, 0);
    int buf = 0;
    float h = 0.f;

    for (int w = 0; w < NW; w++) {
        if (w + 1 < NW) {
            load_win(w + 1, buf ^ 1);
            asm volatile("cp.async.wait_group 1;\n");
        } else {
            asm volatile("cp.async.wait_group 0;\n");
        }
        __syncthreads();

        const float* fDT = s_buf[buf][0];
        const float* fXC = s_buf[buf][1];
        const float* fBC = s_buf[buf][3];
#pragma unroll 4
        for (int t = 0; t < SW; t++) {
            float dtv = fDT[t * 32 + dloc];
            float xv  = fXC[t * 32 + dloc];
            float Bv  = fBC[t * 32 + s];
            float Cv  = fBC[t * 32 + 16 + s];
            float dA  = __expf(dtv * A_s);
            h = fmaf(dA, h, dtv * Bv * xv);
            float p = h * Cv;
            p += __shfl_xor_sync(0xffffffffu, p, 8);
            p += __shfl_xor_sync(0xffffffffu, p, 4);
            p += __shfl_xor_sync(0xffffffffu, p, 2);
            p += __shfl_xor_sync(0xffffffffu, p, 1);
            if (s == 0) s_y[t][dloc] = fmaf(Dd, xv, p);
        }
        __syncthreads();

        const float* fZ = s_buf[buf][2];
        int t0 = w * SW;
#pragma unroll
        for (int k = 0; k < 4; k++) {
            int idx = tid + k * 512;
            int t = idx >> 5, dd = idx & 31;
            float yv = s_y[t][dd];
            float zv = fZ[t * 32 + dd];
            float sig = 1.f / (1.f + __expf(-zv));
            yv *= zv * sig;
            __half hi, lo; split2h(yv, hi, lo);
            __half* o = e_y + (size_t)(b * TT + t0 + t) * 2 * DIN + d0 + dd;
            o[0] = hi; o[DIN] = lo;
        }
        __syncthreads();
        buf ^= 1;
    }
}

// ==================== launch ====================
extern "C" void kernel_launch(void* const* d_in, const int* in_sizes, int n_in,
                              void* d_out, int out_size) {
    const float* x          = (const float*)d_in[0];
    const float* norm_w     = (const float*)d_in[1];
    const float* norm_b     = (const float*)d_in[2];
    const float* in_proj_w  = (const float*)d_in[3];
    const float* conv_w     = (const float*)d_in[4];
    const float* conv_b     = (const float*)d_in[5];
    const float* x_proj_w   = (const float*)d_in[6];
    const float* dt_proj_w  = (const float*)d_in[7];
    const float* dt_proj_b  = (const float*)d_in[8];
    const float* A_log      = (const float*)d_in[9];
    const float* Dvec       = (const float*)d_in[10];
    const float* out_proj_w = (const float*)d_in[11];
    float* out = (float*)d_out;

    float *xz, *xdbl, *dt, *part;
    __half *exn, *ew1, *exc, *ew2, *edtr, *ew3, *ey, *ew4;
    cudaGetSymbolAddress((void**)&xz,   g_xz);
    cudaGetSymbolAddress((void**)&xdbl, g_xdbl);
    cudaGetSymbolAddress((void**)&dt,   g_dt);
    cudaGetSymbolAddress((void**)&part, g_part);
    cudaGetSymbolAddress((void**)&exn,  e_xn);
    cudaGetSymbolAddress((void**)&ew1,  e_w1);
    cudaGetSymbolAddress((void**)&exc,  e_xc);
    cudaGetSymbolAddress((void**)&ew2,  e_w2);
    cudaGetSymbolAddress((void**)&edtr, e_dtr);
    cudaGetSymbolAddress((void**)&ew3,  e_w3);
    cudaGetSymbolAddress((void**)&ey,   e_y);
    cudaGetSymbolAddress((void**)&ew4,  e_w4);

    const int smem128 = 3 * (128 * 128 + 128 * 128);   // 98304
    const int smem64  = 3 * (128 * 128 + 64 * 128);    // 73728
    cudaFuncSetAttribute(gemm_mma<0, 128>, cudaFuncAttributeMaxDynamicSharedMemorySize, smem128);
    cudaFuncSetAttribute(gemm_mma<1, 128>, cudaFuncAttributeMaxDynamicSharedMemorySize, smem128);
    cudaFuncSetAttribute(gemm_mma<3, 128>, cudaFuncAttributeMaxDynamicSharedMemorySize, smem128);
    cudaFuncSetAttribute(gemm_mma<2, 64>,  cudaFuncAttributeMaxDynamicSharedMemorySize, smem64);

    // 1. in_proj weight convert ([hi,hi])
    convert2_kernel<0><<<(2 * DIN * CC / 2 + 255) / 256, 256>>>(in_proj_w, ew1, CC, 2 * DIN * CC / 2);
    // 2. LayerNorm -> e_xn [hi,lo]
    ln_kernel<<<TOKS, 256>>>(x, norm_w, norm_b);
    // 3. out_proj weight convert
    convert2_kernel<0><<<(CC * DIN / 2 + 255) / 256, 256>>>(out_proj_w, ew4, DIN, CC * DIN / 2);
    // 4. in_proj GEMM  (PROFILED LAUNCH)  Kext = 2*CC
    gemm_mma<0, 128><<<dim3((2 * DIN) / 128, TOKS / 128), 256, smem128>>>(
        exn, 2 * CC, ew1, 2 * CC, xz, 2 * DIN, TOKS, 2 * DIN, 2 * CC, nullptr, nullptr);
    // 5. conv + SiLU -> g_xc + e_xc [hi,lo]
    conv_silu_kernel<<<(TOKS * DIN) / 256, 256>>>(conv_w, conv_b);
    // 6. x_proj weight convert
    convert2_kernel<0><<<(XDBL * DIN / 2 + 255) / 256, 256>>>(x_proj_w, ew2, DIN, XDBL * DIN / 2);
    // 7. x_proj split-K GEMM  Kext = 2*DIN = 4096, 16-way -> 256 per split
    gemm_mma<3, 128><<<dim3(1, TOKS / 128, SPLITK), 256, smem128>>>(
        exc, 2 * DIN, ew2, 2 * DIN, part, XDBL, TOKS, XDBL, 2 * DIN, nullptr, nullptr);
    // 8. reduce partials + fused dt_raw ext convert
    reduce_part_kernel<<<(TOKS * XDBL + 255) / 256, 256>>>();
    // 9. dt_proj weight convert
    convert2_kernel<0><<<(DIN * DTRANK / 2 + 255) / 256, 256>>>(dt_proj_w, ew3, DTRANK, DIN * DTRANK / 2);
    // 10. dt_proj + softplus  Kext = 2*DTRANK = 128
    gemm_mma<1, 128><<<dim3(DIN / 128, TOKS / 128), 256, smem128>>>(
        edtr, 2 * DTRANK, ew3, 2 * DTRANK, dt, DIN, TOKS, DIN, 2 * DTRANK, dt_proj_b, nullptr);
    // 11. selective scan + gate
    scan_kernel<<<(BB * DIN) / 32, 512>>>(A_log, Dvec);
    // 12. out_proj + residual transposed store  Kext = 2*DIN
    gemm_mma<2, 64><<<dim3(CC / 64, TOKS / 128), 256, smem64>>>(
        ey, 2 * DIN, ew4, 2 * DIN, out, 0, TOKS, CC, 2 * DIN, nullptr, x);
}